// round 12
// baseline (speedup 1.0000x reference)
#include <cuda_runtime.h>
#include <cuda_fp16.h>
#include <math.h>
#include <stdint.h>

#define D_ 1024
#define H_ 16
#define HD_ 64
#define HL_ 8
#define STRIDE_ 128
#define DFF_ 4096
#define B_ 4
#define S_ 4096
#define M_ (B_*S_)
#define NB_ (S_/STRIDE_)
#define SCALE_ 0.125f

// ---------------- scratch (device globals; no allocation allowed) ----------------
__device__ __half g_qkvh[(size_t)M_ * 3072];   // reused as f2 (half) after attention
__device__ float  g_attn[M_ * D_];
__device__ float  g_bqkv[3072];
__device__ __half g_hx[M_ * D_];               // src half; reused as proj (half) after QKV GEMM
__device__ __half g_hao[M_ * D_];
__device__ __half g_hattn[M_ * D_];
__device__ __half g_hh[(size_t)M_ * DFF_];
__device__ __half g_wh[12 * 1024 * 1024 + 1024 * 1024];  // packed half weights

#define WQKV_OFF 0                      // [3072][1024]
#define WO_OFF   (3072*1024)            // [1024][1024]
#define W1_OFF   (4096*1024)            // [4096][1024]
#define W2_OFF   (8192*1024)            // [1024][4096]

// ============================ helpers =============================================
__device__ __forceinline__ uint32_t smem_u32(const void* p) {
    uint32_t a;
    asm("{ .reg .u64 t; cvta.to.shared.u64 t, %1; cvt.u32.u64 %0, t; }" : "=r"(a) : "l"(p));
    return a;
}
__device__ __forceinline__ void cp16(uint32_t dst, const void* src) {
    asm volatile("cp.async.cg.shared.global [%0], [%1], 16;" :: "r"(dst), "l"(src));
}
#define CP_COMMIT()  asm volatile("cp.async.commit_group;" ::: "memory")
#define CP_WAIT1()   asm volatile("cp.async.wait_group 1;" ::: "memory")
#define CP_WAIT0()   asm volatile("cp.async.wait_group 0;" ::: "memory")

__device__ __forceinline__ void ldmat_x4(uint32_t& r0, uint32_t& r1, uint32_t& r2, uint32_t& r3,
                                         uint32_t addr) {
    asm volatile("ldmatrix.sync.aligned.m8n8.x4.shared.b16 {%0,%1,%2,%3}, [%4];"
        : "=r"(r0), "=r"(r1), "=r"(r2), "=r"(r3) : "r"(addr));
}
__device__ __forceinline__ void ldmat_x4t(uint32_t& r0, uint32_t& r1, uint32_t& r2, uint32_t& r3,
                                          uint32_t addr) {
    asm volatile("ldmatrix.sync.aligned.m8n8.x4.trans.shared.b16 {%0,%1,%2,%3}, [%4];"
        : "=r"(r0), "=r"(r1), "=r"(r2), "=r"(r3) : "r"(addr));
}
__device__ __forceinline__ void mma_f16(float& c0, float& c1, float& c2, float& c3,
                                        uint32_t a0, uint32_t a1, uint32_t a2, uint32_t a3,
                                        uint32_t b0, uint32_t b1) {
    asm volatile(
        "mma.sync.aligned.m16n8k16.row.col.f32.f16.f16.f32 "
        "{%0,%1,%2,%3}, {%4,%5,%6,%7}, {%8,%9}, {%0,%1,%2,%3};"
        : "+f"(c0), "+f"(c1), "+f"(c2), "+f"(c3)
        : "r"(a0), "r"(a1), "r"(a2), "r"(a3), "r"(b0), "r"(b1));
}
__device__ __forceinline__ uint32_t packh2(float x, float y) {
    __half2 h = __floats2half2_rn(x, y);
    return *(uint32_t*)&h;
}

// ============================ fp16 mma.sync GEMM v5 ===============================
// C[M,N] = A[M,K] @ BT[N,K]^T + bias.  A, BT half, K-contiguous.
// CTA tile 128x128, 8 warps (2x4) each 64x32.
// BK=64 halfs, 3-stage cp.async ring, ONE sync per 64-K chunk (16 epochs @ K=1024).
// MODE 0: fp32 out + bias.  MODE 1: half relu(out+bias).  MODE 2: half out+bias.
#define BKH 64
#define BSTR 72                          // halfs per smem row (144B, conflict-free)
#define ASTG (128 * BSTR)                // halfs per operand stage
#define STG  (2 * ASTG)
#define NSTAGE 3
#define SMEM_GEMM (NSTAGE * STG * 2)     // 110592 bytes

template<int MODE>
__global__ __launch_bounds__(256, 2) void hgemm_kernel(
    const __half* __restrict__ A, const __half* __restrict__ BT,
    const float* __restrict__ bias, void* __restrict__ Cv,
    int M, int N, int K)
{
    extern __shared__ __half smh[];
    const uint32_t sbase = smem_u32(smh);

    const int tid = threadIdx.x;
    const int wid = tid >> 5, lane = tid & 31;
    const int g = lane >> 2, qc = lane & 3;
    const int n0 = blockIdx.x * 128, m0 = blockIdx.y * 128;
    const int warpM = wid & 1, warpN = wid >> 1;

    // gmem->smem: 2 threads per row, each copies 32 halfs (4x cp16)
    const int row2 = tid >> 1;
    const int hc = (tid & 1) * 32;
    const __half* Ag = A  + (size_t)(m0 + row2) * K + hc;
    const __half* Bg = BT + (size_t)(n0 + row2) * K + hc;
    const uint32_t soff = (uint32_t)(row2 * BSTR + hc) * 2;

    const int nch = K / BKH;

    #pragma unroll
    for (int pc = 0; pc < NSTAGE - 1; pc++) {
        const uint32_t sa = sbase + pc * (STG * 2);
        const uint32_t sb = sa + ASTG * 2;
        const __half* Ap = Ag + pc * BKH;
        const __half* Bp = Bg + pc * BKH;
        #pragma unroll
        for (int i = 0; i < 4; i++) {
            cp16(sa + soff + i * 16, Ap + i * 8);
            cp16(sb + soff + i * 16, Bp + i * 8);
        }
        CP_COMMIT();
    }

    float cfr[4][4][4];
    #pragma unroll
    for (int mt = 0; mt < 4; mt++)
        #pragma unroll
        for (int nt = 0; nt < 4; nt++)
            #pragma unroll
            for (int r = 0; r < 4; r++) cfr[mt][nt][r] = 0.f;

    const uint32_t a_lrow = (uint32_t)(warpM * 64 + (lane & 15));
    const uint32_t a_kofs = (uint32_t)((lane >> 4) << 3);
    const uint32_t b_lrow = (uint32_t)(warpN * 32 + ((lane >> 4) << 3) + (lane & 7));
    const uint32_t b_kofs = (uint32_t)(((lane >> 3) & 1) << 3);

    for (int c = 0; c < nch; c++) {
        const int stg = (c % NSTAGE);
        const uint32_t sa = sbase + stg * (STG * 2);
        const uint32_t sb = sa + ASTG * 2;

        CP_WAIT1();
        __syncthreads();

        #pragma unroll
        for (int ks = 0; ks < 4; ks++) {
            uint32_t af[4][4];
            #pragma unroll
            for (int mt = 0; mt < 4; mt++) {
                uint32_t addr = sa + ((a_lrow + mt * 16) * BSTR + ks * 16 + a_kofs) * 2;
                ldmat_x4(af[mt][0], af[mt][1], af[mt][2], af[mt][3], addr);
            }
            uint32_t bf[4][2];
            #pragma unroll
            for (int p = 0; p < 2; p++) {
                uint32_t addr = sb + ((b_lrow + p * 16) * BSTR + ks * 16 + b_kofs) * 2;
                ldmat_x4(bf[2 * p][0], bf[2 * p][1], bf[2 * p + 1][0], bf[2 * p + 1][1], addr);
            }
            #pragma unroll
            for (int mt = 0; mt < 4; mt++)
                #pragma unroll
                for (int nt = 0; nt < 4; nt++)
                    mma_f16(cfr[mt][nt][0], cfr[mt][nt][1], cfr[mt][nt][2], cfr[mt][nt][3],
                            af[mt][0], af[mt][1], af[mt][2], af[mt][3],
                            bf[nt][0], bf[nt][1]);
        }

        const int pc = c + NSTAGE - 1;
        if (pc < nch) {
            const int ps = pc % NSTAGE;
            const uint32_t pa = sbase + ps * (STG * 2);
            const uint32_t pb = pa + ASTG * 2;
            const __half* Ap = Ag + (size_t)pc * BKH;
            const __half* Bp = Bg + (size_t)pc * BKH;
            #pragma unroll
            for (int i = 0; i < 4; i++) {
                cp16(pa + soff + i * 16, Ap + i * 8);
                cp16(pb + soff + i * 16, Bp + i * 8);
            }
        }
        CP_COMMIT();
    }

    #pragma unroll
    for (int mt = 0; mt < 4; mt++) {
        const int row = m0 + warpM * 64 + mt * 16 + g;
        #pragma unroll
        for (int nt = 0; nt < 4; nt++) {
            const int col = n0 + warpN * 32 + nt * 8 + qc * 2;
            float b0 = __ldg(&bias[col]), b1 = __ldg(&bias[col + 1]);
            float v0 = cfr[mt][nt][0] + b0, v1 = cfr[mt][nt][1] + b1;
            float v2 = cfr[mt][nt][2] + b0, v3 = cfr[mt][nt][3] + b1;
            if (MODE == 0) {
                float* Cf = (float*)Cv;
                *(float2*)&Cf[(size_t)row * N + col]       = make_float2(v0, v1);
                *(float2*)&Cf[(size_t)(row + 8) * N + col] = make_float2(v2, v3);
            } else {
                __half* Ch = (__half*)Cv;
                if (MODE == 1) {
                    v0 = fmaxf(v0, 0.f); v1 = fmaxf(v1, 0.f);
                    v2 = fmaxf(v2, 0.f); v3 = fmaxf(v3, 0.f);
                }
                *(__half2*)&Ch[(size_t)row * N + col]       = __floats2half2_rn(v0, v1);
                *(__half2*)&Ch[(size_t)(row + 8) * N + col] = __floats2half2_rn(v2, v3);
            }
        }
    }
}

// ---------------- merged prep: src f2h + 6 weight transposes + bias pack -----------
__global__ __launch_bounds__(256) void prep_kernel(
    const float* __restrict__ src, __half* __restrict__ hx,
    const float* __restrict__ Wq, const float* __restrict__ Wk,
    const float* __restrict__ Wv, const float* __restrict__ Wo,
    const float* __restrict__ W1, const float* __restrict__ W2,
    const float* __restrict__ bq, const float* __restrict__ bk,
    const float* __restrict__ bv,
    __half* __restrict__ wh, float* __restrict__ bqkv)
{
    const int id = blockIdx.x;
    if (id < 16384) {
        const int i = id * 256 + threadIdx.x;
        float4 v = ((const float4*)src)[i];
        __half2* o = (__half2*)hx;
        o[i * 2]     = __floats2half2_rn(v.x, v.y);
        o[i * 2 + 1] = __floats2half2_rn(v.z, v.w);
        return;
    }
    if (id == 28672) {
        for (int j = threadIdx.x; j < 3072; j += 256)
            bqkv[j] = (j < 1024) ? bq[j] : (j < 2048) ? bk[j - 1024] : bv[j - 2048];
        return;
    }

    const int tidb = id - 16384;
    const float* in;
    __half* outp;
    int K, N, bx, by;
    if (tidb < 4096) {
        const int m = tidb >> 10, lid = tidb & 1023;
        in   = (m == 0) ? Wq : (m == 1) ? Wk : (m == 2) ? Wv : Wo;
        outp = wh + ((m == 3) ? WO_OFF : WQKV_OFF + m * 1024 * 1024);
        K = 1024; N = 1024; bx = lid & 31; by = lid >> 5;
    } else if (tidb < 8192) {
        const int lid = tidb - 4096;
        in = W1; outp = wh + W1_OFF;
        K = 1024; N = 4096; bx = lid & 127; by = lid >> 7;
    } else {
        const int lid = tidb - 8192;
        in = W2; outp = wh + W2_OFF;
        K = 4096; N = 1024; bx = lid & 31; by = lid >> 5;
    }

    __shared__ float t[32][33];
    const int n0 = bx * 32, k0 = by * 32;
    const int tx = threadIdx.x & 31, ty = threadIdx.x >> 5;
    #pragma unroll
    for (int i = 0; i < 4; i++)
        t[ty + i * 8][tx] = in[(size_t)(k0 + ty + i * 8) * N + n0 + tx];
    __syncthreads();
    #pragma unroll
    for (int i = 0; i < 4; i++)
        outp[(size_t)(n0 + ty + i * 8) * K + k0 + tx] = __float2half(t[tx][ty + i * 8]);
}

// ============================ fused tensor-core attention =========================
#define ATS 72
#define SMEM_ATT (5 * 128 * ATS * 2)   // 92160

__global__ __launch_bounds__(256, 2) void attn_mma(
    const __half* __restrict__ qkv, __half* __restrict__ out)
{
    extern __shared__ __half sm[];
    const int tid = threadIdx.x;
    const int w = tid >> 5, lane = tid & 31;
    const int g = lane >> 2, qc = lane & 3;

    const uint32_t a_row = (uint32_t)(w * 16 + (lane & 15));
    const uint32_t a_k   = (uint32_t)((lane >> 4) << 3);
    const uint32_t b_rA  = (uint32_t)(((lane >> 4) << 3) + (lane & 7));
    const uint32_t b_k   = (uint32_t)(((lane >> 3) & 1) << 3);
    const uint32_t v_r   = (uint32_t)(lane & 15);
    const uint32_t v_c   = (uint32_t)((lane >> 4) << 3);

    if (blockIdx.x < 1024) {
        __half* sQ = sm;
        __half* sK = sm + 128 * ATS;
        __half* sV = sm + 2 * 128 * ATS;
        const uint32_t uQ = smem_u32(sQ), uK = smem_u32(sK), uV = smem_u32(sV);

        const int bid = blockIdx.x;
        const int h = bid % HL_;
        const int n = (bid / HL_) % NB_;
        const int b = bid / (HL_ * NB_);
        const int tok0 = b * S_ + n * STRIDE_;

        {
            const int r2 = tid >> 1, hs = (tid & 1) * 32;
            const __half* base = qkv + (size_t)(tok0 + r2) * 3072 + h * 64 + hs;
            const uint32_t dst = (uint32_t)(r2 * ATS + hs) * 2;
            #pragma unroll
            for (int i = 0; i < 4; i++) {
                cp16(uQ + dst + i * 16, base + i * 8);
                cp16(uK + dst + i * 16, base + 1024 + i * 8);
                cp16(uV + dst + i * 16, base + 2048 + i * 8);
            }
            CP_COMMIT();
        }
        CP_WAIT0();
        __syncthreads();

        float sc[16][4];
        #pragma unroll
        for (int nt = 0; nt < 16; nt++)
            #pragma unroll
            for (int r = 0; r < 4; r++) sc[nt][r] = 0.f;

        #pragma unroll
        for (int ks = 0; ks < 4; ks++) {
            uint32_t aq[4];
            ldmat_x4(aq[0], aq[1], aq[2], aq[3], uQ + (a_row * ATS + ks * 16 + a_k) * 2);
            #pragma unroll
            for (int p = 0; p < 8; p++) {
                uint32_t r0, r1, r2, r3;
                ldmat_x4(r0, r1, r2, r3, uK + ((p * 16 + b_rA) * ATS + ks * 16 + b_k) * 2);
                mma_f16(sc[2*p][0], sc[2*p][1], sc[2*p][2], sc[2*p][3],
                        aq[0], aq[1], aq[2], aq[3], r0, r1);
                mma_f16(sc[2*p+1][0], sc[2*p+1][1], sc[2*p+1][2], sc[2*p+1][3],
                        aq[0], aq[1], aq[2], aq[3], r2, r3);
            }
        }

        float m0 = -1e30f, m1 = -1e30f;
        #pragma unroll
        for (int nt = 0; nt < 16; nt++) {
            sc[nt][0] *= SCALE_; sc[nt][1] *= SCALE_;
            sc[nt][2] *= SCALE_; sc[nt][3] *= SCALE_;
            m0 = fmaxf(m0, fmaxf(sc[nt][0], sc[nt][1]));
            m1 = fmaxf(m1, fmaxf(sc[nt][2], sc[nt][3]));
        }
        m0 = fmaxf(m0, __shfl_xor_sync(0xffffffffu, m0, 1));
        m0 = fmaxf(m0, __shfl_xor_sync(0xffffffffu, m0, 2));
        m1 = fmaxf(m1, __shfl_xor_sync(0xffffffffu, m1, 1));
        m1 = fmaxf(m1, __shfl_xor_sync(0xffffffffu, m1, 2));
        float l0 = 0.f, l1 = 0.f;
        #pragma unroll
        for (int nt = 0; nt < 16; nt++) {
            sc[nt][0] = __expf(sc[nt][0] - m0); sc[nt][1] = __expf(sc[nt][1] - m0);
            sc[nt][2] = __expf(sc[nt][2] - m1); sc[nt][3] = __expf(sc[nt][3] - m1);
            l0 += sc[nt][0] + sc[nt][1];
            l1 += sc[nt][2] + sc[nt][3];
        }
        l0 += __shfl_xor_sync(0xffffffffu, l0, 1);
        l0 += __shfl_xor_sync(0xffffffffu, l0, 2);
        l1 += __shfl_xor_sync(0xffffffffu, l1, 1);
        l1 += __shfl_xor_sync(0xffffffffu, l1, 2);
        const float rl0 = 1.0f / l0, rl1 = 1.0f / l1;
        #pragma unroll
        for (int nt = 0; nt < 16; nt++) {
            sc[nt][0] *= rl0; sc[nt][1] *= rl0;
            sc[nt][2] *= rl1; sc[nt][3] *= rl1;
        }

        float oc[8][4];
        #pragma unroll
        for (int nt = 0; nt < 8; nt++)
            #pragma unroll
            for (int r = 0; r < 4; r++) oc[nt][r] = 0.f;

        #pragma unroll
        for (int kk = 0; kk < 8; kk++) {
            uint32_t a0 = packh2(sc[2*kk][0],   sc[2*kk][1]);
            uint32_t a1 = packh2(sc[2*kk][2],   sc[2*kk][3]);
            uint32_t a2 = packh2(sc[2*kk+1][0], sc[2*kk+1][1]);
            uint32_t a3 = packh2(sc[2*kk+1][2], sc[2*kk+1][3]);
            #pragma unroll
            for (int jp = 0; jp < 4; jp++) {
                uint32_t r0, r1, r2, r3;
                ldmat_x4t(r0, r1, r2, r3, uV + ((kk * 16 + v_r) * ATS + jp * 16 + v_c) * 2);
                mma_f16(oc[2*jp][0], oc[2*jp][1], oc[2*jp][2], oc[2*jp][3],
                        a0, a1, a2, a3, r0, r1);
                mma_f16(oc[2*jp+1][0], oc[2*jp+1][1], oc[2*jp+1][2], oc[2*jp+1][3],
                        a0, a1, a2, a3, r2, r3);
            }
        }

        const int row = tok0 + w * 16 + g;
        __half* op  = out + (size_t)row * 1024 + h * 64;
        __half* op8 = out + (size_t)(row + 8) * 1024 + h * 64;
        #pragma unroll
        for (int nt = 0; nt < 8; nt++) {
            *(__half2*)(op  + nt * 8 + qc * 2) = __floats2half2_rn(oc[nt][0], oc[nt][1]);
            *(__half2*)(op8 + nt * 8 + qc * 2) = __floats2half2_rn(oc[nt][2], oc[nt][3]);
        }
    } else {
        __half* sQ = sm;
        __half* sK0 = sm + 128 * ATS;
        __half* sV0 = sm + 3 * 128 * ATS;
        const uint32_t uQ = smem_u32(sQ);
        const uint32_t uK[2] = { smem_u32(sK0), smem_u32(sK0 + 128 * ATS) };
        const uint32_t uV[2] = { smem_u32(sV0), smem_u32(sV0 + 128 * ATS) };

        const int bid = blockIdx.x - 1024;
        const int hg = bid & 7;
        const int qt = (bid >> 3) & 31;
        const int b  = bid >> 8;
        const int head = HL_ + hg;
        const int tok0 = b * S_ + qt * 128;

        const int r2 = tid >> 1, hs = (tid & 1) * 32;
        const uint32_t dst = (uint32_t)(r2 * ATS + hs) * 2;

        {
            const __half* qb = qkv + (size_t)(tok0 + r2) * 3072 + head * 64 + hs;
            #pragma unroll
            for (int i = 0; i < 4; i++) cp16(uQ + dst + i * 16, qb + i * 8);
            const int kidx = r2;
            const int pos = ((kidx >> 5) << 7) + 96 + (kidx & 31);
            const __half* kb = qkv + (size_t)(b * S_ + pos) * 3072 + 1024 + head * 64 + hs;
            #pragma unroll
            for (int i = 0; i < 4; i++) {
                cp16(uK[0] + dst + i * 16, kb + i * 8);
                cp16(uV[0] + dst + i * 16, kb + 1024 + i * 8);
            }
            CP_COMMIT();
        }

        float m0 = -1e30f, m1 = -1e30f, l0 = 0.f, l1 = 0.f;
        float oc[8][4];
        #pragma unroll
        for (int nt = 0; nt < 8; nt++)
            #pragma unroll
            for (int r = 0; r < 4; r++) oc[nt][r] = 0.f;

        for (int t = 0; t < 8; t++) {
            const int buf = t & 1;
            if (t + 1 < 8) {
                const int kidx = (t + 1) * 128 + r2;
                const int pos = ((kidx >> 5) << 7) + 96 + (kidx & 31);
                const __half* kb = qkv + (size_t)(b * S_ + pos) * 3072 + 1024 + head * 64 + hs;
                const int nb = buf ^ 1;
                #pragma unroll
                for (int i = 0; i < 4; i++) {
                    cp16(uK[nb] + dst + i * 16, kb + i * 8);
                    cp16(uV[nb] + dst + i * 16, kb + 1024 + i * 8);
                }
                CP_COMMIT();
                CP_WAIT1();
            } else {
                CP_WAIT0();
            }
            __syncthreads();

            float sc[16][4];
            #pragma unroll
            for (int nt = 0; nt < 16; nt++)
                #pragma unroll
                for (int r = 0; r < 4; r++) sc[nt][r] = 0.f;

            #pragma unroll
            for (int ks = 0; ks < 4; ks++) {
                uint32_t aq[4];
                ldmat_x4(aq[0], aq[1], aq[2], aq[3], uQ + (a_row * ATS + ks * 16 + a_k) * 2);
                #pragma unroll
                for (int p = 0; p < 8; p++) {
                    uint32_t r0, r1, r2b, r3;
                    ldmat_x4(r0, r1, r2b, r3, uK[buf] + ((p * 16 + b_rA) * ATS + ks * 16 + b_k) * 2);
                    mma_f16(sc[2*p][0], sc[2*p][1], sc[2*p][2], sc[2*p][3],
                            aq[0], aq[1], aq[2], aq[3], r0, r1);
                    mma_f16(sc[2*p+1][0], sc[2*p+1][1], sc[2*p+1][2], sc[2*p+1][3],
                            aq[0], aq[1], aq[2], aq[3], r2b, r3);
                }
            }

            float tm0 = -1e30f, tm1 = -1e30f;
            #pragma unroll
            for (int nt = 0; nt < 16; nt++) {
                sc[nt][0] *= SCALE_; sc[nt][1] *= SCALE_;
                sc[nt][2] *= SCALE_; sc[nt][3] *= SCALE_;
                tm0 = fmaxf(tm0, fmaxf(sc[nt][0], sc[nt][1]));
                tm1 = fmaxf(tm1, fmaxf(sc[nt][2], sc[nt][3]));
            }
            tm0 = fmaxf(tm0, __shfl_xor_sync(0xffffffffu, tm0, 1));
            tm0 = fmaxf(tm0, __shfl_xor_sync(0xffffffffu, tm0, 2));
            tm1 = fmaxf(tm1, __shfl_xor_sync(0xffffffffu, tm1, 1));
            tm1 = fmaxf(tm1, __shfl_xor_sync(0xffffffffu, tm1, 2));
            const float mn0 = fmaxf(m0, tm0), mn1 = fmaxf(m1, tm1);
            const float f0 = __expf(m0 - mn0), f1 = __expf(m1 - mn1);
            m0 = mn0; m1 = mn1;

            float ts0 = 0.f, ts1 = 0.f;
            #pragma unroll
            for (int nt = 0; nt < 16; nt++) {
                sc[nt][0] = __expf(sc[nt][0] - mn0); sc[nt][1] = __expf(sc[nt][1] - mn0);
                sc[nt][2] = __expf(sc[nt][2] - mn1); sc[nt][3] = __expf(sc[nt][3] - mn1);
                ts0 += sc[nt][0] + sc[nt][1];
                ts1 += sc[nt][2] + sc[nt][3];
            }
            ts0 += __shfl_xor_sync(0xffffffffu, ts0, 1);
            ts0 += __shfl_xor_sync(0xffffffffu, ts0, 2);
            ts1 += __shfl_xor_sync(0xffffffffu, ts1, 1);
            ts1 += __shfl_xor_sync(0xffffffffu, ts1, 2);
            l0 = l0 * f0 + ts0;
            l1 = l1 * f1 + ts1;

            #pragma unroll
            for (int nt = 0; nt < 8; nt++) {
                oc[nt][0] *= f0; oc[nt][1] *= f0;
                oc[nt][2] *= f1; oc[nt][3] *= f1;
            }

            #pragma unroll
            for (int kk = 0; kk < 8; kk++) {
                uint32_t a0 = packh2(sc[2*kk][0],   sc[2*kk][1]);
                uint32_t a1 = packh2(sc[2*kk][2],   sc[2*kk][3]);
                uint32_t a2 = packh2(sc[2*kk+1][0], sc[2*kk+1][1]);
                uint32_t a3 = packh2(sc[2*kk+1][2], sc[2*kk+1][3]);
                #pragma unroll
                for (int jp = 0; jp < 4; jp++) {
                    uint32_t r0, r1, r2b, r3;
                    ldmat_x4t(r0, r1, r2b, r3, uV[buf] + ((kk * 16 + v_r) * ATS + jp * 16 + v_c) * 2);
                    mma_f16(oc[2*jp][0], oc[2*jp][1], oc[2*jp][2], oc[2*jp][3],
                            a0, a1, a2, a3, r0, r1);
                    mma_f16(oc[2*jp+1][0], oc[2*jp+1][1], oc[2*jp+1][2], oc[2*jp+1][3],
                            a0, a1, a2, a3, r2b, r3);
                }
            }
            __syncthreads();
        }

        const float rl0 = 1.0f / l0, rl1 = 1.0f / l1;
        const int row = tok0 + w * 16 + g;
        __half* op  = out + (size_t)row * 1024 + head * 64;
        __half* op8 = out + (size_t)(row + 8) * 1024 + head * 64;
        #pragma unroll
        for (int nt = 0; nt < 8; nt++) {
            *(__half2*)(op  + nt * 8 + qc * 2) = __floats2half2_rn(oc[nt][0] * rl0, oc[nt][1] * rl0);
            *(__half2*)(op8 + nt * 8 + qc * 2) = __floats2half2_rn(oc[nt][2] * rl1, oc[nt][3] * rl1);
        }
    }
}

// ---------------- fused residual + layernorm (y is half) ---------------------------
__global__ __launch_bounds__(256) void add_ln_h_kernel(
    const float* __restrict__ x, const __half* __restrict__ yh,
    const float* __restrict__ g, const float* __restrict__ bb,
    float* __restrict__ out, __half* __restrict__ out_h)
{
    const int row = blockIdx.x;
    const int tid = threadIdx.x;
    const int lane = tid & 31, warp = tid >> 5;

    float4 xv = ((const float4*)x)[(size_t)row * 256 + tid];
    const __half2* y2 = (const __half2*)yh;
    float2 y01 = __half22float2(y2[(size_t)row * 512 + tid * 2]);
    float2 y23 = __half22float2(y2[(size_t)row * 512 + tid * 2 + 1]);
    float4 vval;
    vval.x = xv.x + y01.x; vval.y = xv.y + y01.y;
    vval.z = xv.z + y23.x; vval.w = xv.w + y23.y;

    float s  = vval.x + vval.y + vval.z + vval.w;
    float sq = vval.x * vval.x + vval.y * vval.y + vval.z * vval.z + vval.w * vval.w;
    #pragma unroll
    for (int o = 16; o; o >>= 1) {
        s  += __shfl_xor_sync(0xffffffffu, s, o);
        sq += __shfl_xor_sync(0xffffffffu, sq, o);
    }
    __shared__ float ws[8], wq[8];
    __shared__ float mu_s, rstd_s;
    if (lane == 0) { ws[warp] = s; wq[warp] = sq; }
    __syncthreads();
    if (warp == 0) {
        float a  = (lane < 8) ? ws[lane] : 0.f;
        float b2 = (lane < 8) ? wq[lane] : 0.f;
        #pragma unroll
        for (int o = 4; o; o >>= 1) {
            a  += __shfl_xor_sync(0xffffffffu, a, o);
            b2 += __shfl_xor_sync(0xffffffffu, b2, o);
        }
        if (lane == 0) {
            float mu = a * (1.0f / 1024.0f);
            float var = b2 * (1.0f / 1024.0f) - mu * mu;
            mu_s = mu;
            rstd_s = rsqrtf(var + 1e-6f);
        }
    }
    __syncthreads();
    float mu = mu_s, rstd = rstd_s;

    float4 gv = ((const float4*)g)[tid];
    float4 bv = ((const float4*)bb)[tid];
    float4 r;
    r.x = gv.x * (vval.x - mu) * rstd + bv.x;
    r.y = gv.y * (vval.y - mu) * rstd + bv.y;
    r.z = gv.z * (vval.z - mu) * rstd + bv.z;
    r.w = gv.w * (vval.w - mu) * rstd + bv.w;
    ((float4*)out)[(size_t)row * 256 + tid] = r;
    if (out_h) {
        __half2* oh = (__half2*)out_h;
        oh[(size_t)row * 512 + tid * 2]     = __floats2half2_rn(r.x, r.y);
        oh[(size_t)row * 512 + tid * 2 + 1] = __floats2half2_rn(r.z, r.w);
    }
}

// ---------------- launcher ---------------------------------------------------------
extern "C" void kernel_launch(void* const* d_in, const int* in_sizes, int n_in,
                              void* d_out, int out_size)
{
    const float* src  = (const float*)d_in[0];
    const float* Wq   = (const float*)d_in[2];
    const float* bq   = (const float*)d_in[3];
    const float* Wk   = (const float*)d_in[4];
    const float* bk   = (const float*)d_in[5];
    const float* Wv   = (const float*)d_in[6];
    const float* bv   = (const float*)d_in[7];
    const float* Wo   = (const float*)d_in[8];
    const float* bo   = (const float*)d_in[9];
    const float* ln1g = (const float*)d_in[10];
    const float* ln1b = (const float*)d_in[11];
    const float* W1   = (const float*)d_in[12];
    const float* b1   = (const float*)d_in[13];
    const float* W2   = (const float*)d_in[14];
    const float* b2   = (const float*)d_in[15];
    const float* ln2g = (const float*)d_in[16];
    const float* ln2b = (const float*)d_in[17];
    float* out = (float*)d_out;

    float *attn, *bqkv;
    __half *qkvh, *hx, *hao, *hattn, *hh, *wh;
    cudaGetSymbolAddress((void**)&qkvh,  g_qkvh);
    cudaGetSymbolAddress((void**)&attn,  g_attn);
    cudaGetSymbolAddress((void**)&bqkv,  g_bqkv);
    cudaGetSymbolAddress((void**)&hx,    g_hx);
    cudaGetSymbolAddress((void**)&hao,   g_hao);
    cudaGetSymbolAddress((void**)&hattn, g_hattn);
    cudaGetSymbolAddress((void**)&hh,    g_hh);
    cudaGetSymbolAddress((void**)&wh,    g_wh);

    __half* proj_h = hx;     // reuse: hx dead after QKV GEMM
    __half* f2_h   = qkvh;   // reuse: qkvh dead after attention

    cudaFuncSetAttribute(attn_mma,        cudaFuncAttributeMaxDynamicSharedMemorySize, SMEM_ATT);
    cudaFuncSetAttribute(hgemm_kernel<0>, cudaFuncAttributeMaxDynamicSharedMemorySize, SMEM_GEMM);
    cudaFuncSetAttribute(hgemm_kernel<1>, cudaFuncAttributeMaxDynamicSharedMemorySize, SMEM_GEMM);
    cudaFuncSetAttribute(hgemm_kernel<2>, cudaFuncAttributeMaxDynamicSharedMemorySize, SMEM_GEMM);

    // #1: all prep (src f2h + weight transposes + bias pack)
    prep_kernel<<<28673, 256>>>(src, hx, Wq, Wk, Wv, Wo, W1, W2, bq, bk, bv, wh, bqkv);

    // #2: fused QKV projection -> half [M,3072]
    hgemm_kernel<2><<<dim3(24, 128), 256, SMEM_GEMM>>>(hx, wh + WQKV_OFF, bqkv, qkvh, M_, 3072, D_);

    // #3: fused tensor-core sparse attention -> hao (half)
    attn_mma<<<2048, 256, SMEM_ATT>>>(qkvh, hao);

    // #4: output projection -> half (reuses hx)
    hgemm_kernel<2><<<dim3(8, 128), 256, SMEM_GEMM>>>(hao, wh + WO_OFF, bo, proj_h, M_, D_, D_);

    // #5: attn = LN1(src + proj); half copy for FFN1
    add_ln_h_kernel<<<M_, 256>>>(src, proj_h, ln1g, ln1b, attn, hattn);

    // #6,#7: FFN
    hgemm_kernel<1><<<dim3(32, 128), 256, SMEM_GEMM>>>(hattn, wh + W1_OFF, b1, hh, M_, DFF_, D_);
    hgemm_kernel<2><<<dim3(8, 128), 256, SMEM_GEMM>>>(hh, wh + W2_OFF, b2, f2_h, M_, D_, DFF_);

    // #8: out = LN2(attn + ffn)
    add_ln_h_kernel<<<M_, 256>>>(attn, f2_h, ln2g, ln2b, out, nullptr);
}

// round 13
// speedup vs baseline: 1.1126x; 1.1126x over previous
#include <cuda_runtime.h>
#include <cuda_fp16.h>
#include <math.h>
#include <stdint.h>

#define D_ 1024
#define H_ 16
#define HD_ 64
#define HL_ 8
#define STRIDE_ 128
#define DFF_ 4096
#define B_ 4
#define S_ 4096
#define M_ (B_*S_)
#define NB_ (S_/STRIDE_)
#define SCALE_ 0.125f

// ---------------- scratch (device globals; no allocation allowed) ----------------
__device__ __half g_qkvh[(size_t)M_ * 3072];   // reused as f2 (half) after attention
__device__ float  g_attn[M_ * D_];
__device__ float  g_bqkv[3072];
__device__ __half g_hx[M_ * D_];               // src half; reused as proj (half) after QKV GEMM
__device__ __half g_hao[M_ * D_];
__device__ __half g_hattn[M_ * D_];
__device__ __half g_hh[(size_t)M_ * DFF_];
__device__ __half g_wh[12 * 1024 * 1024 + 1024 * 1024];  // packed half weights

#define WQKV_OFF 0                      // [3072][1024]
#define WO_OFF   (3072*1024)            // [1024][1024]
#define W1_OFF   (4096*1024)            // [4096][1024]
#define W2_OFF   (8192*1024)            // [1024][4096]

// ============================ helpers =============================================
__device__ __forceinline__ uint32_t smem_u32(const void* p) {
    uint32_t a;
    asm("{ .reg .u64 t; cvta.to.shared.u64 t, %1; cvt.u32.u64 %0, t; }" : "=r"(a) : "l"(p));
    return a;
}
__device__ __forceinline__ void cp16(uint32_t dst, const void* src) {
    asm volatile("cp.async.cg.shared.global [%0], [%1], 16;" :: "r"(dst), "l"(src));
}
#define CP_COMMIT()  asm volatile("cp.async.commit_group;" ::: "memory")
#define CP_WAIT3()   asm volatile("cp.async.wait_group 3;" ::: "memory")
#define CP_WAIT1()   asm volatile("cp.async.wait_group 1;" ::: "memory")
#define CP_WAIT0()   asm volatile("cp.async.wait_group 0;" ::: "memory")

__device__ __forceinline__ void ldmat_x4(uint32_t& r0, uint32_t& r1, uint32_t& r2, uint32_t& r3,
                                         uint32_t addr) {
    asm volatile("ldmatrix.sync.aligned.m8n8.x4.shared.b16 {%0,%1,%2,%3}, [%4];"
        : "=r"(r0), "=r"(r1), "=r"(r2), "=r"(r3) : "r"(addr));
}
__device__ __forceinline__ void ldmat_x4t(uint32_t& r0, uint32_t& r1, uint32_t& r2, uint32_t& r3,
                                          uint32_t addr) {
    asm volatile("ldmatrix.sync.aligned.m8n8.x4.trans.shared.b16 {%0,%1,%2,%3}, [%4];"
        : "=r"(r0), "=r"(r1), "=r"(r2), "=r"(r3) : "r"(addr));
}
__device__ __forceinline__ void mma_f16(float& c0, float& c1, float& c2, float& c3,
                                        uint32_t a0, uint32_t a1, uint32_t a2, uint32_t a3,
                                        uint32_t b0, uint32_t b1) {
    asm volatile(
        "mma.sync.aligned.m16n8k16.row.col.f32.f16.f16.f32 "
        "{%0,%1,%2,%3}, {%4,%5,%6,%7}, {%8,%9}, {%0,%1,%2,%3};"
        : "+f"(c0), "+f"(c1), "+f"(c2), "+f"(c3)
        : "r"(a0), "r"(a1), "r"(a2), "r"(a3), "r"(b0), "r"(b1));
}
__device__ __forceinline__ uint32_t packh2(float x, float y) {
    __half2 h = __floats2half2_rn(x, y);
    return *(uint32_t*)&h;
}

// ============================ fp16 mma.sync GEMM v6 ===============================
// Mainloop = round-7 verified shape (BK=32, BSTR=40, 8 warps x 64x32, wait-2 cadence)
// but with a 5-deep cp.async ring (wait_group 3): 3 prefetch chunks in flight.
// smem = 5 * 20480 = 102400 B/CTA -> 2 CTAs/SM.
// MODE 0: fp32 out + bias.  MODE 1: half relu(out+bias).  MODE 2: half out+bias.
#define BKH 32
#define BSTR 40
#define ASTG (128 * BSTR)
#define STG  (2 * ASTG)
#define NSTAGE 5
#define SMEM_GEMM (NSTAGE * STG * 2)     // 102400 bytes

template<int MODE>
__global__ __launch_bounds__(256, 2) void hgemm_kernel(
    const __half* __restrict__ A, const __half* __restrict__ BT,
    const float* __restrict__ bias, void* __restrict__ Cv,
    int M, int N, int K)
{
    extern __shared__ __half smh[];
    const uint32_t sbase = smem_u32(smh);

    const int tid = threadIdx.x;
    const int wid = tid >> 5, lane = tid & 31;
    const int g = lane >> 2, qc = lane & 3;
    const int n0 = blockIdx.x * 128, m0 = blockIdx.y * 128;
    const int warpM = wid & 1, warpN = wid >> 1;

    const int row2 = tid >> 1;
    const int hc = (tid & 1) * 16;
    const __half* Ag = A  + (size_t)(m0 + row2) * K + hc;
    const __half* Bg = BT + (size_t)(n0 + row2) * K + hc;
    const uint32_t soff = (uint32_t)(row2 * BSTR + hc) * 2;

    const int nch = K / BKH;

    #pragma unroll
    for (int pc = 0; pc < NSTAGE - 1; pc++) {
        const uint32_t sa = sbase + pc * (STG * 2);
        const uint32_t sb = sa + ASTG * 2;
        const __half* Ap = Ag + pc * BKH;
        const __half* Bp = Bg + pc * BKH;
        cp16(sa + soff,      Ap);
        cp16(sa + soff + 16, Ap + 8);
        cp16(sb + soff,      Bp);
        cp16(sb + soff + 16, Bp + 8);
        CP_COMMIT();
    }

    float cfr[4][4][4];
    #pragma unroll
    for (int mt = 0; mt < 4; mt++)
        #pragma unroll
        for (int nt = 0; nt < 4; nt++)
            #pragma unroll
            for (int r = 0; r < 4; r++) cfr[mt][nt][r] = 0.f;

    const uint32_t a_lrow = (uint32_t)(warpM * 64 + (lane & 15));
    const uint32_t a_kofs = (uint32_t)((lane >> 4) << 3);
    const uint32_t b_lrow = (uint32_t)(warpN * 32 + ((lane >> 4) << 3) + (lane & 7));
    const uint32_t b_kofs = (uint32_t)(((lane >> 3) & 1) << 3);

    for (int c = 0; c < nch; c++) {
        const int stg = c % NSTAGE;
        const uint32_t sa = sbase + stg * (STG * 2);
        const uint32_t sb = sa + ASTG * 2;

        CP_WAIT3();
        __syncthreads();

        #pragma unroll
        for (int ks = 0; ks < 2; ks++) {
            uint32_t af[4][4];
            #pragma unroll
            for (int mt = 0; mt < 4; mt++) {
                uint32_t addr = sa + ((a_lrow + mt * 16) * BSTR + ks * 16 + a_kofs) * 2;
                ldmat_x4(af[mt][0], af[mt][1], af[mt][2], af[mt][3], addr);
            }
            uint32_t bf[4][2];
            #pragma unroll
            for (int p = 0; p < 2; p++) {
                uint32_t addr = sb + ((b_lrow + p * 16) * BSTR + ks * 16 + b_kofs) * 2;
                ldmat_x4(bf[2 * p][0], bf[2 * p][1], bf[2 * p + 1][0], bf[2 * p + 1][1], addr);
            }
            #pragma unroll
            for (int mt = 0; mt < 4; mt++)
                #pragma unroll
                for (int nt = 0; nt < 4; nt++)
                    mma_f16(cfr[mt][nt][0], cfr[mt][nt][1], cfr[mt][nt][2], cfr[mt][nt][3],
                            af[mt][0], af[mt][1], af[mt][2], af[mt][3],
                            bf[nt][0], bf[nt][1]);
        }

        const int pc = c + NSTAGE - 1;
        if (pc < nch) {
            const int ps = pc % NSTAGE;
            const uint32_t pa = sbase + ps * (STG * 2);
            const uint32_t pb = pa + ASTG * 2;
            const __half* Ap = Ag + (size_t)pc * BKH;
            const __half* Bp = Bg + (size_t)pc * BKH;
            cp16(pa + soff,      Ap);
            cp16(pa + soff + 16, Ap + 8);
            cp16(pb + soff,      Bp);
            cp16(pb + soff + 16, Bp + 8);
        }
        CP_COMMIT();
    }

    #pragma unroll
    for (int mt = 0; mt < 4; mt++) {
        const int row = m0 + warpM * 64 + mt * 16 + g;
        #pragma unroll
        for (int nt = 0; nt < 4; nt++) {
            const int col = n0 + warpN * 32 + nt * 8 + qc * 2;
            float b0 = __ldg(&bias[col]), b1 = __ldg(&bias[col + 1]);
            float v0 = cfr[mt][nt][0] + b0, v1 = cfr[mt][nt][1] + b1;
            float v2 = cfr[mt][nt][2] + b0, v3 = cfr[mt][nt][3] + b1;
            if (MODE == 0) {
                float* Cf = (float*)Cv;
                *(float2*)&Cf[(size_t)row * N + col]       = make_float2(v0, v1);
                *(float2*)&Cf[(size_t)(row + 8) * N + col] = make_float2(v2, v3);
            } else {
                __half* Ch = (__half*)Cv;
                if (MODE == 1) {
                    v0 = fmaxf(v0, 0.f); v1 = fmaxf(v1, 0.f);
                    v2 = fmaxf(v2, 0.f); v3 = fmaxf(v3, 0.f);
                }
                *(__half2*)&Ch[(size_t)row * N + col]       = __floats2half2_rn(v0, v1);
                *(__half2*)&Ch[(size_t)(row + 8) * N + col] = __floats2half2_rn(v2, v3);
            }
        }
    }
}

// ---------------- merged prep: src f2h + 6 weight transposes + bias pack -----------
__global__ __launch_bounds__(256) void prep_kernel(
    const float* __restrict__ src, __half* __restrict__ hx,
    const float* __restrict__ Wq, const float* __restrict__ Wk,
    const float* __restrict__ Wv, const float* __restrict__ Wo,
    const float* __restrict__ W1, const float* __restrict__ W2,
    const float* __restrict__ bq, const float* __restrict__ bk,
    const float* __restrict__ bv,
    __half* __restrict__ wh, float* __restrict__ bqkv)
{
    const int id = blockIdx.x;
    if (id < 16384) {
        const int i = id * 256 + threadIdx.x;
        float4 v = ((const float4*)src)[i];
        __half2* o = (__half2*)hx;
        o[i * 2]     = __floats2half2_rn(v.x, v.y);
        o[i * 2 + 1] = __floats2half2_rn(v.z, v.w);
        return;
    }
    if (id == 28672) {
        for (int j = threadIdx.x; j < 3072; j += 256)
            bqkv[j] = (j < 1024) ? bq[j] : (j < 2048) ? bk[j - 1024] : bv[j - 2048];
        return;
    }

    const int tidb = id - 16384;
    const float* in;
    __half* outp;
    int K, N, bx, by;
    if (tidb < 4096) {
        const int m = tidb >> 10, lid = tidb & 1023;
        in   = (m == 0) ? Wq : (m == 1) ? Wk : (m == 2) ? Wv : Wo;
        outp = wh + ((m == 3) ? WO_OFF : WQKV_OFF + m * 1024 * 1024);
        K = 1024; N = 1024; bx = lid & 31; by = lid >> 5;
    } else if (tidb < 8192) {
        const int lid = tidb - 4096;
        in = W1; outp = wh + W1_OFF;
        K = 1024; N = 4096; bx = lid & 127; by = lid >> 7;
    } else {
        const int lid = tidb - 8192;
        in = W2; outp = wh + W2_OFF;
        K = 4096; N = 1024; bx = lid & 31; by = lid >> 5;
    }

    __shared__ float t[32][33];
    const int n0 = bx * 32, k0 = by * 32;
    const int tx = threadIdx.x & 31, ty = threadIdx.x >> 5;
    #pragma unroll
    for (int i = 0; i < 4; i++)
        t[ty + i * 8][tx] = in[(size_t)(k0 + ty + i * 8) * N + n0 + tx];
    __syncthreads();
    #pragma unroll
    for (int i = 0; i < 4; i++)
        outp[(size_t)(n0 + ty + i * 8) * K + k0 + tx] = __float2half(t[tx][ty + i * 8]);
}

// ============================ fused tensor-core attention =========================
#define ATS 72
#define SMEM_ATT (5 * 128 * ATS * 2)   // 92160

__global__ __launch_bounds__(256, 2) void attn_mma(
    const __half* __restrict__ qkv, __half* __restrict__ out)
{
    extern __shared__ __half sm[];
    const int tid = threadIdx.x;
    const int w = tid >> 5, lane = tid & 31;
    const int g = lane >> 2, qc = lane & 3;

    const uint32_t a_row = (uint32_t)(w * 16 + (lane & 15));
    const uint32_t a_k   = (uint32_t)((lane >> 4) << 3);
    const uint32_t b_rA  = (uint32_t)(((lane >> 4) << 3) + (lane & 7));
    const uint32_t b_k   = (uint32_t)(((lane >> 3) & 1) << 3);
    const uint32_t v_r   = (uint32_t)(lane & 15);
    const uint32_t v_c   = (uint32_t)((lane >> 4) << 3);

    if (blockIdx.x < 1024) {
        __half* sQ = sm;
        __half* sK = sm + 128 * ATS;
        __half* sV = sm + 2 * 128 * ATS;
        const uint32_t uQ = smem_u32(sQ), uK = smem_u32(sK), uV = smem_u32(sV);

        const int bid = blockIdx.x;
        const int h = bid % HL_;
        const int n = (bid / HL_) % NB_;
        const int b = bid / (HL_ * NB_);
        const int tok0 = b * S_ + n * STRIDE_;

        {
            const int r2 = tid >> 1, hs = (tid & 1) * 32;
            const __half* base = qkv + (size_t)(tok0 + r2) * 3072 + h * 64 + hs;
            const uint32_t dst = (uint32_t)(r2 * ATS + hs) * 2;
            #pragma unroll
            for (int i = 0; i < 4; i++) {
                cp16(uQ + dst + i * 16, base + i * 8);
                cp16(uK + dst + i * 16, base + 1024 + i * 8);
                cp16(uV + dst + i * 16, base + 2048 + i * 8);
            }
            CP_COMMIT();
        }
        CP_WAIT0();
        __syncthreads();

        float sc[16][4];
        #pragma unroll
        for (int nt = 0; nt < 16; nt++)
            #pragma unroll
            for (int r = 0; r < 4; r++) sc[nt][r] = 0.f;

        #pragma unroll
        for (int ks = 0; ks < 4; ks++) {
            uint32_t aq[4];
            ldmat_x4(aq[0], aq[1], aq[2], aq[3], uQ + (a_row * ATS + ks * 16 + a_k) * 2);
            #pragma unroll
            for (int p = 0; p < 8; p++) {
                uint32_t r0, r1, r2, r3;
                ldmat_x4(r0, r1, r2, r3, uK + ((p * 16 + b_rA) * ATS + ks * 16 + b_k) * 2);
                mma_f16(sc[2*p][0], sc[2*p][1], sc[2*p][2], sc[2*p][3],
                        aq[0], aq[1], aq[2], aq[3], r0, r1);
                mma_f16(sc[2*p+1][0], sc[2*p+1][1], sc[2*p+1][2], sc[2*p+1][3],
                        aq[0], aq[1], aq[2], aq[3], r2, r3);
            }
        }

        float m0 = -1e30f, m1 = -1e30f;
        #pragma unroll
        for (int nt = 0; nt < 16; nt++) {
            sc[nt][0] *= SCALE_; sc[nt][1] *= SCALE_;
            sc[nt][2] *= SCALE_; sc[nt][3] *= SCALE_;
            m0 = fmaxf(m0, fmaxf(sc[nt][0], sc[nt][1]));
            m1 = fmaxf(m1, fmaxf(sc[nt][2], sc[nt][3]));
        }
        m0 = fmaxf(m0, __shfl_xor_sync(0xffffffffu, m0, 1));
        m0 = fmaxf(m0, __shfl_xor_sync(0xffffffffu, m0, 2));
        m1 = fmaxf(m1, __shfl_xor_sync(0xffffffffu, m1, 1));
        m1 = fmaxf(m1, __shfl_xor_sync(0xffffffffu, m1, 2));
        float l0 = 0.f, l1 = 0.f;
        #pragma unroll
        for (int nt = 0; nt < 16; nt++) {
            sc[nt][0] = __expf(sc[nt][0] - m0); sc[nt][1] = __expf(sc[nt][1] - m0);
            sc[nt][2] = __expf(sc[nt][2] - m1); sc[nt][3] = __expf(sc[nt][3] - m1);
            l0 += sc[nt][0] + sc[nt][1];
            l1 += sc[nt][2] + sc[nt][3];
        }
        l0 += __shfl_xor_sync(0xffffffffu, l0, 1);
        l0 += __shfl_xor_sync(0xffffffffu, l0, 2);
        l1 += __shfl_xor_sync(0xffffffffu, l1, 1);
        l1 += __shfl_xor_sync(0xffffffffu, l1, 2);
        const float rl0 = 1.0f / l0, rl1 = 1.0f / l1;
        #pragma unroll
        for (int nt = 0; nt < 16; nt++) {
            sc[nt][0] *= rl0; sc[nt][1] *= rl0;
            sc[nt][2] *= rl1; sc[nt][3] *= rl1;
        }

        float oc[8][4];
        #pragma unroll
        for (int nt = 0; nt < 8; nt++)
            #pragma unroll
            for (int r = 0; r < 4; r++) oc[nt][r] = 0.f;

        #pragma unroll
        for (int kk = 0; kk < 8; kk++) {
            uint32_t a0 = packh2(sc[2*kk][0],   sc[2*kk][1]);
            uint32_t a1 = packh2(sc[2*kk][2],   sc[2*kk][3]);
            uint32_t a2 = packh2(sc[2*kk+1][0], sc[2*kk+1][1]);
            uint32_t a3 = packh2(sc[2*kk+1][2], sc[2*kk+1][3]);
            #pragma unroll
            for (int jp = 0; jp < 4; jp++) {
                uint32_t r0, r1, r2, r3;
                ldmat_x4t(r0, r1, r2, r3, uV + ((kk * 16 + v_r) * ATS + jp * 16 + v_c) * 2);
                mma_f16(oc[2*jp][0], oc[2*jp][1], oc[2*jp][2], oc[2*jp][3],
                        a0, a1, a2, a3, r0, r1);
                mma_f16(oc[2*jp+1][0], oc[2*jp+1][1], oc[2*jp+1][2], oc[2*jp+1][3],
                        a0, a1, a2, a3, r2, r3);
            }
        }

        const int row = tok0 + w * 16 + g;
        __half* op  = out + (size_t)row * 1024 + h * 64;
        __half* op8 = out + (size_t)(row + 8) * 1024 + h * 64;
        #pragma unroll
        for (int nt = 0; nt < 8; nt++) {
            *(__half2*)(op  + nt * 8 + qc * 2) = __floats2half2_rn(oc[nt][0], oc[nt][1]);
            *(__half2*)(op8 + nt * 8 + qc * 2) = __floats2half2_rn(oc[nt][2], oc[nt][3]);
        }
    } else {
        __half* sQ = sm;
        __half* sK0 = sm + 128 * ATS;
        __half* sV0 = sm + 3 * 128 * ATS;
        const uint32_t uQ = smem_u32(sQ);
        const uint32_t uK[2] = { smem_u32(sK0), smem_u32(sK0 + 128 * ATS) };
        const uint32_t uV[2] = { smem_u32(sV0), smem_u32(sV0 + 128 * ATS) };

        const int bid = blockIdx.x - 1024;
        const int hg = bid & 7;
        const int qt = (bid >> 3) & 31;
        const int b  = bid >> 8;
        const int head = HL_ + hg;
        const int tok0 = b * S_ + qt * 128;

        const int r2 = tid >> 1, hs = (tid & 1) * 32;
        const uint32_t dst = (uint32_t)(r2 * ATS + hs) * 2;

        {
            const __half* qb = qkv + (size_t)(tok0 + r2) * 3072 + head * 64 + hs;
            #pragma unroll
            for (int i = 0; i < 4; i++) cp16(uQ + dst + i * 16, qb + i * 8);
            const int kidx = r2;
            const int pos = ((kidx >> 5) << 7) + 96 + (kidx & 31);
            const __half* kb = qkv + (size_t)(b * S_ + pos) * 3072 + 1024 + head * 64 + hs;
            #pragma unroll
            for (int i = 0; i < 4; i++) {
                cp16(uK[0] + dst + i * 16, kb + i * 8);
                cp16(uV[0] + dst + i * 16, kb + 1024 + i * 8);
            }
            CP_COMMIT();
        }

        float m0 = -1e30f, m1 = -1e30f, l0 = 0.f, l1 = 0.f;
        float oc[8][4];
        #pragma unroll
        for (int nt = 0; nt < 8; nt++)
            #pragma unroll
            for (int r = 0; r < 4; r++) oc[nt][r] = 0.f;

        for (int t = 0; t < 8; t++) {
            const int buf = t & 1;
            if (t + 1 < 8) {
                const int kidx = (t + 1) * 128 + r2;
                const int pos = ((kidx >> 5) << 7) + 96 + (kidx & 31);
                const __half* kb = qkv + (size_t)(b * S_ + pos) * 3072 + 1024 + head * 64 + hs;
                const int nb = buf ^ 1;
                #pragma unroll
                for (int i = 0; i < 4; i++) {
                    cp16(uK[nb] + dst + i * 16, kb + i * 8);
                    cp16(uV[nb] + dst + i * 16, kb + 1024 + i * 8);
                }
                CP_COMMIT();
                CP_WAIT1();
            } else {
                CP_WAIT0();
            }
            __syncthreads();

            float sc[16][4];
            #pragma unroll
            for (int nt = 0; nt < 16; nt++)
                #pragma unroll
                for (int r = 0; r < 4; r++) sc[nt][r] = 0.f;

            #pragma unroll
            for (int ks = 0; ks < 4; ks++) {
                uint32_t aq[4];
                ldmat_x4(aq[0], aq[1], aq[2], aq[3], uQ + (a_row * ATS + ks * 16 + a_k) * 2);
                #pragma unroll
                for (int p = 0; p < 8; p++) {
                    uint32_t r0, r1, r2b, r3;
                    ldmat_x4(r0, r1, r2b, r3, uK[buf] + ((p * 16 + b_rA) * ATS + ks * 16 + b_k) * 2);
                    mma_f16(sc[2*p][0], sc[2*p][1], sc[2*p][2], sc[2*p][3],
                            aq[0], aq[1], aq[2], aq[3], r0, r1);
                    mma_f16(sc[2*p+1][0], sc[2*p+1][1], sc[2*p+1][2], sc[2*p+1][3],
                            aq[0], aq[1], aq[2], aq[3], r2b, r3);
                }
            }

            float tm0 = -1e30f, tm1 = -1e30f;
            #pragma unroll
            for (int nt = 0; nt < 16; nt++) {
                sc[nt][0] *= SCALE_; sc[nt][1] *= SCALE_;
                sc[nt][2] *= SCALE_; sc[nt][3] *= SCALE_;
                tm0 = fmaxf(tm0, fmaxf(sc[nt][0], sc[nt][1]));
                tm1 = fmaxf(tm1, fmaxf(sc[nt][2], sc[nt][3]));
            }
            tm0 = fmaxf(tm0, __shfl_xor_sync(0xffffffffu, tm0, 1));
            tm0 = fmaxf(tm0, __shfl_xor_sync(0xffffffffu, tm0, 2));
            tm1 = fmaxf(tm1, __shfl_xor_sync(0xffffffffu, tm1, 1));
            tm1 = fmaxf(tm1, __shfl_xor_sync(0xffffffffu, tm1, 2));
            const float mn0 = fmaxf(m0, tm0), mn1 = fmaxf(m1, tm1);
            const float f0 = __expf(m0 - mn0), f1 = __expf(m1 - mn1);
            m0 = mn0; m1 = mn1;

            float ts0 = 0.f, ts1 = 0.f;
            #pragma unroll
            for (int nt = 0; nt < 16; nt++) {
                sc[nt][0] = __expf(sc[nt][0] - mn0); sc[nt][1] = __expf(sc[nt][1] - mn0);
                sc[nt][2] = __expf(sc[nt][2] - mn1); sc[nt][3] = __expf(sc[nt][3] - mn1);
                ts0 += sc[nt][0] + sc[nt][1];
                ts1 += sc[nt][2] + sc[nt][3];
            }
            ts0 += __shfl_xor_sync(0xffffffffu, ts0, 1);
            ts0 += __shfl_xor_sync(0xffffffffu, ts0, 2);
            ts1 += __shfl_xor_sync(0xffffffffu, ts1, 1);
            ts1 += __shfl_xor_sync(0xffffffffu, ts1, 2);
            l0 = l0 * f0 + ts0;
            l1 = l1 * f1 + ts1;

            #pragma unroll
            for (int nt = 0; nt < 8; nt++) {
                oc[nt][0] *= f0; oc[nt][1] *= f0;
                oc[nt][2] *= f1; oc[nt][3] *= f1;
            }

            #pragma unroll
            for (int kk = 0; kk < 8; kk++) {
                uint32_t a0 = packh2(sc[2*kk][0],   sc[2*kk][1]);
                uint32_t a1 = packh2(sc[2*kk][2],   sc[2*kk][3]);
                uint32_t a2 = packh2(sc[2*kk+1][0], sc[2*kk+1][1]);
                uint32_t a3 = packh2(sc[2*kk+1][2], sc[2*kk+1][3]);
                #pragma unroll
                for (int jp = 0; jp < 4; jp++) {
                    uint32_t r0, r1, r2b, r3;
                    ldmat_x4t(r0, r1, r2b, r3, uV[buf] + ((kk * 16 + v_r) * ATS + jp * 16 + v_c) * 2);
                    mma_f16(oc[2*jp][0], oc[2*jp][1], oc[2*jp][2], oc[2*jp][3],
                            a0, a1, a2, a3, r0, r1);
                    mma_f16(oc[2*jp+1][0], oc[2*jp+1][1], oc[2*jp+1][2], oc[2*jp+1][3],
                            a0, a1, a2, a3, r2b, r3);
                }
            }
            __syncthreads();
        }

        const float rl0 = 1.0f / l0, rl1 = 1.0f / l1;
        const int row = tok0 + w * 16 + g;
        __half* op  = out + (size_t)row * 1024 + head * 64;
        __half* op8 = out + (size_t)(row + 8) * 1024 + head * 64;
        #pragma unroll
        for (int nt = 0; nt < 8; nt++) {
            *(__half2*)(op  + nt * 8 + qc * 2) = __floats2half2_rn(oc[nt][0] * rl0, oc[nt][1] * rl0);
            *(__half2*)(op8 + nt * 8 + qc * 2) = __floats2half2_rn(oc[nt][2] * rl1, oc[nt][3] * rl1);
        }
    }
}

// ---------------- fused residual + layernorm (y is half) ---------------------------
__global__ __launch_bounds__(256) void add_ln_h_kernel(
    const float* __restrict__ x, const __half* __restrict__ yh,
    const float* __restrict__ g, const float* __restrict__ bb,
    float* __restrict__ out, __half* __restrict__ out_h)
{
    const int row = blockIdx.x;
    const int tid = threadIdx.x;
    const int lane = tid & 31, warp = tid >> 5;

    float4 xv = ((const float4*)x)[(size_t)row * 256 + tid];
    const __half2* y2 = (const __half2*)yh;
    float2 y01 = __half22float2(y2[(size_t)row * 512 + tid * 2]);
    float2 y23 = __half22float2(y2[(size_t)row * 512 + tid * 2 + 1]);
    float4 vval;
    vval.x = xv.x + y01.x; vval.y = xv.y + y01.y;
    vval.z = xv.z + y23.x; vval.w = xv.w + y23.y;

    float s  = vval.x + vval.y + vval.z + vval.w;
    float sq = vval.x * vval.x + vval.y * vval.y + vval.z * vval.z + vval.w * vval.w;
    #pragma unroll
    for (int o = 16; o; o >>= 1) {
        s  += __shfl_xor_sync(0xffffffffu, s, o);
        sq += __shfl_xor_sync(0xffffffffu, sq, o);
    }
    __shared__ float ws[8], wq[8];
    __shared__ float mu_s, rstd_s;
    if (lane == 0) { ws[warp] = s; wq[warp] = sq; }
    __syncthreads();
    if (warp == 0) {
        float a  = (lane < 8) ? ws[lane] : 0.f;
        float b2 = (lane < 8) ? wq[lane] : 0.f;
        #pragma unroll
        for (int o = 4; o; o >>= 1) {
            a  += __shfl_xor_sync(0xffffffffu, a, o);
            b2 += __shfl_xor_sync(0xffffffffu, b2, o);
        }
        if (lane == 0) {
            float mu = a * (1.0f / 1024.0f);
            float var = b2 * (1.0f / 1024.0f) - mu * mu;
            mu_s = mu;
            rstd_s = rsqrtf(var + 1e-6f);
        }
    }
    __syncthreads();
    float mu = mu_s, rstd = rstd_s;

    float4 gv = ((const float4*)g)[tid];
    float4 bv = ((const float4*)bb)[tid];
    float4 r;
    r.x = gv.x * (vval.x - mu) * rstd + bv.x;
    r.y = gv.y * (vval.y - mu) * rstd + bv.y;
    r.z = gv.z * (vval.z - mu) * rstd + bv.z;
    r.w = gv.w * (vval.w - mu) * rstd + bv.w;
    ((float4*)out)[(size_t)row * 256 + tid] = r;
    if (out_h) {
        __half2* oh = (__half2*)out_h;
        oh[(size_t)row * 512 + tid * 2]     = __floats2half2_rn(r.x, r.y);
        oh[(size_t)row * 512 + tid * 2 + 1] = __floats2half2_rn(r.z, r.w);
    }
}

// ---------------- launcher ---------------------------------------------------------
extern "C" void kernel_launch(void* const* d_in, const int* in_sizes, int n_in,
                              void* d_out, int out_size)
{
    const float* src  = (const float*)d_in[0];
    const float* Wq   = (const float*)d_in[2];
    const float* bq   = (const float*)d_in[3];
    const float* Wk   = (const float*)d_in[4];
    const float* bk   = (const float*)d_in[5];
    const float* Wv   = (const float*)d_in[6];
    const float* bv   = (const float*)d_in[7];
    const float* Wo   = (const float*)d_in[8];
    const float* bo   = (const float*)d_in[9];
    const float* ln1g = (const float*)d_in[10];
    const float* ln1b = (const float*)d_in[11];
    const float* W1   = (const float*)d_in[12];
    const float* b1   = (const float*)d_in[13];
    const float* W2   = (const float*)d_in[14];
    const float* b2   = (const float*)d_in[15];
    const float* ln2g = (const float*)d_in[16];
    const float* ln2b = (const float*)d_in[17];
    float* out = (float*)d_out;

    float *attn, *bqkv;
    __half *qkvh, *hx, *hao, *hattn, *hh, *wh;
    cudaGetSymbolAddress((void**)&qkvh,  g_qkvh);
    cudaGetSymbolAddress((void**)&attn,  g_attn);
    cudaGetSymbolAddress((void**)&bqkv,  g_bqkv);
    cudaGetSymbolAddress((void**)&hx,    g_hx);
    cudaGetSymbolAddress((void**)&hao,   g_hao);
    cudaGetSymbolAddress((void**)&hattn, g_hattn);
    cudaGetSymbolAddress((void**)&hh,    g_hh);
    cudaGetSymbolAddress((void**)&wh,    g_wh);

    __half* proj_h = hx;     // reuse: hx dead after QKV GEMM
    __half* f2_h   = qkvh;   // reuse: qkvh dead after attention

    cudaFuncSetAttribute(attn_mma,        cudaFuncAttributeMaxDynamicSharedMemorySize, SMEM_ATT);
    cudaFuncSetAttribute(hgemm_kernel<0>, cudaFuncAttributeMaxDynamicSharedMemorySize, SMEM_GEMM);
    cudaFuncSetAttribute(hgemm_kernel<1>, cudaFuncAttributeMaxDynamicSharedMemorySize, SMEM_GEMM);
    cudaFuncSetAttribute(hgemm_kernel<2>, cudaFuncAttributeMaxDynamicSharedMemorySize, SMEM_GEMM);

    // #1: all prep (src f2h + weight transposes + bias pack)
    prep_kernel<<<28673, 256>>>(src, hx, Wq, Wk, Wv, Wo, W1, W2, bq, bk, bv, wh, bqkv);

    // #2: fused QKV projection -> half [M,3072]
    hgemm_kernel<2><<<dim3(24, 128), 256, SMEM_GEMM>>>(hx, wh + WQKV_OFF, bqkv, qkvh, M_, 3072, D_);

    // #3: fused tensor-core sparse attention -> hao (half)
    attn_mma<<<2048, 256, SMEM_ATT>>>(qkvh, hao);

    // #4: output projection -> half (reuses hx)
    hgemm_kernel<2><<<dim3(8, 128), 256, SMEM_GEMM>>>(hao, wh + WO_OFF, bo, proj_h, M_, D_, D_);

    // #5: attn = LN1(src + proj); half copy for FFN1
    add_ln_h_kernel<<<M_, 256>>>(src, proj_h, ln1g, ln1b, attn, hattn);

    // #6,#7: FFN
    hgemm_kernel<1><<<dim3(32, 128), 256, SMEM_GEMM>>>(hattn, wh + W1_OFF, b1, hh, M_, DFF_, D_);
    hgemm_kernel<2><<<dim3(8, 128), 256, SMEM_GEMM>>>(hh, wh + W2_OFF, b2, f2_h, M_, D_, DFF_);

    // #8: out = LN2(attn + ffn)
    add_ln_h_kernel<<<M_, 256>>>(attn, f2_h, ln2g, ln2b, out, nullptr);
}

// round 14
// speedup vs baseline: 1.1532x; 1.0366x over previous
#include <cuda_runtime.h>
#include <cuda_fp16.h>
#include <math.h>
#include <stdint.h>

#define D_ 1024
#define H_ 16
#define HD_ 64
#define HL_ 8
#define STRIDE_ 128
#define DFF_ 4096
#define B_ 4
#define S_ 4096
#define M_ (B_*S_)
#define NB_ (S_/STRIDE_)
#define SCALE_ 0.125f

// ---------------- scratch (device globals; no allocation allowed) ----------------
__device__ __half g_qkvh[(size_t)M_ * 3072];   // reused as f2 (half) after attention
__device__ float  g_attn[M_ * D_];
__device__ float  g_bqkv[3072];
__device__ __half g_hx[M_ * D_];               // src half (stays alive through LN1)
__device__ __half g_hao[M_ * D_];
__device__ __half g_hattn[M_ * D_];
__device__ __half g_hh[(size_t)M_ * DFF_];     // proj (half) before FFN1 overwrites with hidden
__device__ __half g_wh[12 * 1024 * 1024 + 1024 * 1024];  // packed half weights

#define WQKV_OFF 0                      // [3072][1024]
#define WO_OFF   (3072*1024)            // [1024][1024]
#define W1_OFF   (4096*1024)            // [4096][1024]
#define W2_OFF   (8192*1024)            // [1024][4096]

// ============================ helpers =============================================
__device__ __forceinline__ uint32_t smem_u32(const void* p) {
    uint32_t a;
    asm("{ .reg .u64 t; cvta.to.shared.u64 t, %1; cvt.u32.u64 %0, t; }" : "=r"(a) : "l"(p));
    return a;
}
__device__ __forceinline__ void cp16(uint32_t dst, const void* src) {
    asm volatile("cp.async.cg.shared.global [%0], [%1], 16;" :: "r"(dst), "l"(src));
}
#define CP_COMMIT()  asm volatile("cp.async.commit_group;" ::: "memory")
#define CP_WAIT2()   asm volatile("cp.async.wait_group 2;" ::: "memory")
#define CP_WAIT1()   asm volatile("cp.async.wait_group 1;" ::: "memory")
#define CP_WAIT0()   asm volatile("cp.async.wait_group 0;" ::: "memory")

__device__ __forceinline__ void ldmat_x4(uint32_t& r0, uint32_t& r1, uint32_t& r2, uint32_t& r3,
                                         uint32_t addr) {
    asm volatile("ldmatrix.sync.aligned.m8n8.x4.shared.b16 {%0,%1,%2,%3}, [%4];"
        : "=r"(r0), "=r"(r1), "=r"(r2), "=r"(r3) : "r"(addr));
}
__device__ __forceinline__ void ldmat_x4t(uint32_t& r0, uint32_t& r1, uint32_t& r2, uint32_t& r3,
                                          uint32_t addr) {
    asm volatile("ldmatrix.sync.aligned.m8n8.x4.trans.shared.b16 {%0,%1,%2,%3}, [%4];"
        : "=r"(r0), "=r"(r1), "=r"(r2), "=r"(r3) : "r"(addr));
}
__device__ __forceinline__ void mma_f16(float& c0, float& c1, float& c2, float& c3,
                                        uint32_t a0, uint32_t a1, uint32_t a2, uint32_t a3,
                                        uint32_t b0, uint32_t b1) {
    asm volatile(
        "mma.sync.aligned.m16n8k16.row.col.f32.f16.f16.f32 "
        "{%0,%1,%2,%3}, {%4,%5,%6,%7}, {%8,%9}, {%0,%1,%2,%3};"
        : "+f"(c0), "+f"(c1), "+f"(c2), "+f"(c3)
        : "r"(a0), "r"(a1), "r"(a2), "r"(a3), "r"(b0), "r"(b1));
}
__device__ __forceinline__ uint32_t packh2(float x, float y) {
    __half2 h = __floats2half2_rn(x, y);
    return *(uint32_t*)&h;
}

// ============================ fp16 mma.sync GEMM (R11 verified config) ============
// C[M,N] = A[M,K] @ BT[N,K]^T + bias.  A, BT half, K-contiguous.
// CTA tile 128x128, 8 warps (2x4) each 64x32, BK=32, 4-stage cp.async ring,
// wait_group 2, 2 CTAs/SM (80KB smem each).
// MODE 0: fp32 out + bias.  MODE 1: half relu(out+bias).  MODE 2: half out+bias.
#define BKH 32
#define BSTR 40
#define ASTG (128 * BSTR)
#define STG  (2 * ASTG)
#define NSTAGE 4
#define SMEM_GEMM (NSTAGE * STG * 2)     // 81920 bytes

template<int MODE>
__global__ __launch_bounds__(256, 2) void hgemm_kernel(
    const __half* __restrict__ A, const __half* __restrict__ BT,
    const float* __restrict__ bias, void* __restrict__ Cv,
    int M, int N, int K)
{
    extern __shared__ __half smh[];
    const uint32_t sbase = smem_u32(smh);

    const int tid = threadIdx.x;
    const int wid = tid >> 5, lane = tid & 31;
    const int g = lane >> 2, qc = lane & 3;
    const int n0 = blockIdx.x * 128, m0 = blockIdx.y * 128;
    const int warpM = wid & 1, warpN = wid >> 1;

    const int row2 = tid >> 1;
    const int hc = (tid & 1) * 16;
    const __half* Ag = A  + (size_t)(m0 + row2) * K + hc;
    const __half* Bg = BT + (size_t)(n0 + row2) * K + hc;
    const uint32_t soff = (uint32_t)(row2 * BSTR + hc) * 2;

    const int nch = K / BKH;

    #pragma unroll
    for (int pc = 0; pc < NSTAGE - 1; pc++) {
        const uint32_t sa = sbase + pc * (STG * 2);
        const uint32_t sb = sa + ASTG * 2;
        const __half* Ap = Ag + pc * BKH;
        const __half* Bp = Bg + pc * BKH;
        cp16(sa + soff,      Ap);
        cp16(sa + soff + 16, Ap + 8);
        cp16(sb + soff,      Bp);
        cp16(sb + soff + 16, Bp + 8);
        CP_COMMIT();
    }

    float cfr[4][4][4];
    #pragma unroll
    for (int mt = 0; mt < 4; mt++)
        #pragma unroll
        for (int nt = 0; nt < 4; nt++)
            #pragma unroll
            for (int r = 0; r < 4; r++) cfr[mt][nt][r] = 0.f;

    const uint32_t a_lrow = (uint32_t)(warpM * 64 + (lane & 15));
    const uint32_t a_kofs = (uint32_t)((lane >> 4) << 3);
    const uint32_t b_lrow = (uint32_t)(warpN * 32 + ((lane >> 4) << 3) + (lane & 7));
    const uint32_t b_kofs = (uint32_t)(((lane >> 3) & 1) << 3);

    for (int c = 0; c < nch; c++) {
        const int stg = c & (NSTAGE - 1);
        const uint32_t sa = sbase + stg * (STG * 2);
        const uint32_t sb = sa + ASTG * 2;

        CP_WAIT2();
        __syncthreads();

        #pragma unroll
        for (int ks = 0; ks < 2; ks++) {
            uint32_t af[4][4];
            #pragma unroll
            for (int mt = 0; mt < 4; mt++) {
                uint32_t addr = sa + ((a_lrow + mt * 16) * BSTR + ks * 16 + a_kofs) * 2;
                ldmat_x4(af[mt][0], af[mt][1], af[mt][2], af[mt][3], addr);
            }
            uint32_t bf[4][2];
            #pragma unroll
            for (int p = 0; p < 2; p++) {
                uint32_t addr = sb + ((b_lrow + p * 16) * BSTR + ks * 16 + b_kofs) * 2;
                ldmat_x4(bf[2 * p][0], bf[2 * p][1], bf[2 * p + 1][0], bf[2 * p + 1][1], addr);
            }
            #pragma unroll
            for (int mt = 0; mt < 4; mt++)
                #pragma unroll
                for (int nt = 0; nt < 4; nt++)
                    mma_f16(cfr[mt][nt][0], cfr[mt][nt][1], cfr[mt][nt][2], cfr[mt][nt][3],
                            af[mt][0], af[mt][1], af[mt][2], af[mt][3],
                            bf[nt][0], bf[nt][1]);
        }

        const int pc = c + NSTAGE - 1;
        if (pc < nch) {
            const int ps = pc & (NSTAGE - 1);
            const uint32_t pa = sbase + ps * (STG * 2);
            const uint32_t pb = pa + ASTG * 2;
            const __half* Ap = Ag + (size_t)pc * BKH;
            const __half* Bp = Bg + (size_t)pc * BKH;
            cp16(pa + soff,      Ap);
            cp16(pa + soff + 16, Ap + 8);
            cp16(pb + soff,      Bp);
            cp16(pb + soff + 16, Bp + 8);
        }
        CP_COMMIT();
    }

    #pragma unroll
    for (int mt = 0; mt < 4; mt++) {
        const int row = m0 + warpM * 64 + mt * 16 + g;
        #pragma unroll
        for (int nt = 0; nt < 4; nt++) {
            const int col = n0 + warpN * 32 + nt * 8 + qc * 2;
            float b0 = __ldg(&bias[col]), b1 = __ldg(&bias[col + 1]);
            float v0 = cfr[mt][nt][0] + b0, v1 = cfr[mt][nt][1] + b1;
            float v2 = cfr[mt][nt][2] + b0, v3 = cfr[mt][nt][3] + b1;
            if (MODE == 0) {
                float* Cf = (float*)Cv;
                *(float2*)&Cf[(size_t)row * N + col]       = make_float2(v0, v1);
                *(float2*)&Cf[(size_t)(row + 8) * N + col] = make_float2(v2, v3);
            } else {
                __half* Ch = (__half*)Cv;
                if (MODE == 1) {
                    v0 = fmaxf(v0, 0.f); v1 = fmaxf(v1, 0.f);
                    v2 = fmaxf(v2, 0.f); v3 = fmaxf(v3, 0.f);
                }
                *(__half2*)&Ch[(size_t)row * N + col]       = __floats2half2_rn(v0, v1);
                *(__half2*)&Ch[(size_t)(row + 8) * N + col] = __floats2half2_rn(v2, v3);
            }
        }
    }
}

// ---------------- merged prep: src f2h + 6 weight transposes + bias pack -----------
__global__ __launch_bounds__(256) void prep_kernel(
    const float* __restrict__ src, __half* __restrict__ hx,
    const float* __restrict__ Wq, const float* __restrict__ Wk,
    const float* __restrict__ Wv, const float* __restrict__ Wo,
    const float* __restrict__ W1, const float* __restrict__ W2,
    const float* __restrict__ bq, const float* __restrict__ bk,
    const float* __restrict__ bv,
    __half* __restrict__ wh, float* __restrict__ bqkv)
{
    const int id = blockIdx.x;
    if (id < 16384) {
        const int i = id * 256 + threadIdx.x;
        float4 v = ((const float4*)src)[i];
        __half2* o = (__half2*)hx;
        o[i * 2]     = __floats2half2_rn(v.x, v.y);
        o[i * 2 + 1] = __floats2half2_rn(v.z, v.w);
        return;
    }
    if (id == 28672) {
        for (int j = threadIdx.x; j < 3072; j += 256)
            bqkv[j] = (j < 1024) ? bq[j] : (j < 2048) ? bk[j - 1024] : bv[j - 2048];
        return;
    }

    const int tidb = id - 16384;
    const float* in;
    __half* outp;
    int K, N, bx, by;
    if (tidb < 4096) {
        const int m = tidb >> 10, lid = tidb & 1023;
        in   = (m == 0) ? Wq : (m == 1) ? Wk : (m == 2) ? Wv : Wo;
        outp = wh + ((m == 3) ? WO_OFF : WQKV_OFF + m * 1024 * 1024);
        K = 1024; N = 1024; bx = lid & 31; by = lid >> 5;
    } else if (tidb < 8192) {
        const int lid = tidb - 4096;
        in = W1; outp = wh + W1_OFF;
        K = 1024; N = 4096; bx = lid & 127; by = lid >> 7;
    } else {
        const int lid = tidb - 8192;
        in = W2; outp = wh + W2_OFF;
        K = 4096; N = 1024; bx = lid & 31; by = lid >> 5;
    }

    __shared__ float t[32][33];
    const int n0 = bx * 32, k0 = by * 32;
    const int tx = threadIdx.x & 31, ty = threadIdx.x >> 5;
    #pragma unroll
    for (int i = 0; i < 4; i++)
        t[ty + i * 8][tx] = in[(size_t)(k0 + ty + i * 8) * N + n0 + tx];
    __syncthreads();
    #pragma unroll
    for (int i = 0; i < 4; i++)
        outp[(size_t)(n0 + ty + i * 8) * K + k0 + tx] = __float2half(t[tx][ty + i * 8]);
}

// ============================ fused tensor-core attention =========================
#define ATS 72
#define SMEM_ATT (5 * 128 * ATS * 2)   // 92160

__global__ __launch_bounds__(256, 2) void attn_mma(
    const __half* __restrict__ qkv, __half* __restrict__ out)
{
    extern __shared__ __half sm[];
    const int tid = threadIdx.x;
    const int w = tid >> 5, lane = tid & 31;
    const int g = lane >> 2, qc = lane & 3;

    const uint32_t a_row = (uint32_t)(w * 16 + (lane & 15));
    const uint32_t a_k   = (uint32_t)((lane >> 4) << 3);
    const uint32_t b_rA  = (uint32_t)(((lane >> 4) << 3) + (lane & 7));
    const uint32_t b_k   = (uint32_t)(((lane >> 3) & 1) << 3);
    const uint32_t v_r   = (uint32_t)(lane & 15);
    const uint32_t v_c   = (uint32_t)((lane >> 4) << 3);

    if (blockIdx.x < 1024) {
        __half* sQ = sm;
        __half* sK = sm + 128 * ATS;
        __half* sV = sm + 2 * 128 * ATS;
        const uint32_t uQ = smem_u32(sQ), uK = smem_u32(sK), uV = smem_u32(sV);

        const int bid = blockIdx.x;
        const int h = bid % HL_;
        const int n = (bid / HL_) % NB_;
        const int b = bid / (HL_ * NB_);
        const int tok0 = b * S_ + n * STRIDE_;

        {
            const int r2 = tid >> 1, hs = (tid & 1) * 32;
            const __half* base = qkv + (size_t)(tok0 + r2) * 3072 + h * 64 + hs;
            const uint32_t dst = (uint32_t)(r2 * ATS + hs) * 2;
            #pragma unroll
            for (int i = 0; i < 4; i++) {
                cp16(uQ + dst + i * 16, base + i * 8);
                cp16(uK + dst + i * 16, base + 1024 + i * 8);
                cp16(uV + dst + i * 16, base + 2048 + i * 8);
            }
            CP_COMMIT();
        }
        CP_WAIT0();
        __syncthreads();

        float sc[16][4];
        #pragma unroll
        for (int nt = 0; nt < 16; nt++)
            #pragma unroll
            for (int r = 0; r < 4; r++) sc[nt][r] = 0.f;

        #pragma unroll
        for (int ks = 0; ks < 4; ks++) {
            uint32_t aq[4];
            ldmat_x4(aq[0], aq[1], aq[2], aq[3], uQ + (a_row * ATS + ks * 16 + a_k) * 2);
            #pragma unroll
            for (int p = 0; p < 8; p++) {
                uint32_t r0, r1, r2, r3;
                ldmat_x4(r0, r1, r2, r3, uK + ((p * 16 + b_rA) * ATS + ks * 16 + b_k) * 2);
                mma_f16(sc[2*p][0], sc[2*p][1], sc[2*p][2], sc[2*p][3],
                        aq[0], aq[1], aq[2], aq[3], r0, r1);
                mma_f16(sc[2*p+1][0], sc[2*p+1][1], sc[2*p+1][2], sc[2*p+1][3],
                        aq[0], aq[1], aq[2], aq[3], r2, r3);
            }
        }

        float m0 = -1e30f, m1 = -1e30f;
        #pragma unroll
        for (int nt = 0; nt < 16; nt++) {
            sc[nt][0] *= SCALE_; sc[nt][1] *= SCALE_;
            sc[nt][2] *= SCALE_; sc[nt][3] *= SCALE_;
            m0 = fmaxf(m0, fmaxf(sc[nt][0], sc[nt][1]));
            m1 = fmaxf(m1, fmaxf(sc[nt][2], sc[nt][3]));
        }
        m0 = fmaxf(m0, __shfl_xor_sync(0xffffffffu, m0, 1));
        m0 = fmaxf(m0, __shfl_xor_sync(0xffffffffu, m0, 2));
        m1 = fmaxf(m1, __shfl_xor_sync(0xffffffffu, m1, 1));
        m1 = fmaxf(m1, __shfl_xor_sync(0xffffffffu, m1, 2));
        float l0 = 0.f, l1 = 0.f;
        #pragma unroll
        for (int nt = 0; nt < 16; nt++) {
            sc[nt][0] = __expf(sc[nt][0] - m0); sc[nt][1] = __expf(sc[nt][1] - m0);
            sc[nt][2] = __expf(sc[nt][2] - m1); sc[nt][3] = __expf(sc[nt][3] - m1);
            l0 += sc[nt][0] + sc[nt][1];
            l1 += sc[nt][2] + sc[nt][3];
        }
        l0 += __shfl_xor_sync(0xffffffffu, l0, 1);
        l0 += __shfl_xor_sync(0xffffffffu, l0, 2);
        l1 += __shfl_xor_sync(0xffffffffu, l1, 1);
        l1 += __shfl_xor_sync(0xffffffffu, l1, 2);
        const float rl0 = 1.0f / l0, rl1 = 1.0f / l1;
        #pragma unroll
        for (int nt = 0; nt < 16; nt++) {
            sc[nt][0] *= rl0; sc[nt][1] *= rl0;
            sc[nt][2] *= rl1; sc[nt][3] *= rl1;
        }

        float oc[8][4];
        #pragma unroll
        for (int nt = 0; nt < 8; nt++)
            #pragma unroll
            for (int r = 0; r < 4; r++) oc[nt][r] = 0.f;

        #pragma unroll
        for (int kk = 0; kk < 8; kk++) {
            uint32_t a0 = packh2(sc[2*kk][0],   sc[2*kk][1]);
            uint32_t a1 = packh2(sc[2*kk][2],   sc[2*kk][3]);
            uint32_t a2 = packh2(sc[2*kk+1][0], sc[2*kk+1][1]);
            uint32_t a3 = packh2(sc[2*kk+1][2], sc[2*kk+1][3]);
            #pragma unroll
            for (int jp = 0; jp < 4; jp++) {
                uint32_t r0, r1, r2, r3;
                ldmat_x4t(r0, r1, r2, r3, uV + ((kk * 16 + v_r) * ATS + jp * 16 + v_c) * 2);
                mma_f16(oc[2*jp][0], oc[2*jp][1], oc[2*jp][2], oc[2*jp][3],
                        a0, a1, a2, a3, r0, r1);
                mma_f16(oc[2*jp+1][0], oc[2*jp+1][1], oc[2*jp+1][2], oc[2*jp+1][3],
                        a0, a1, a2, a3, r2, r3);
            }
        }

        const int row = tok0 + w * 16 + g;
        __half* op  = out + (size_t)row * 1024 + h * 64;
        __half* op8 = out + (size_t)(row + 8) * 1024 + h * 64;
        #pragma unroll
        for (int nt = 0; nt < 8; nt++) {
            *(__half2*)(op  + nt * 8 + qc * 2) = __floats2half2_rn(oc[nt][0], oc[nt][1]);
            *(__half2*)(op8 + nt * 8 + qc * 2) = __floats2half2_rn(oc[nt][2], oc[nt][3]);
        }
    } else {
        __half* sQ = sm;
        __half* sK0 = sm + 128 * ATS;
        __half* sV0 = sm + 3 * 128 * ATS;
        const uint32_t uQ = smem_u32(sQ);
        const uint32_t uK[2] = { smem_u32(sK0), smem_u32(sK0 + 128 * ATS) };
        const uint32_t uV[2] = { smem_u32(sV0), smem_u32(sV0 + 128 * ATS) };

        const int bid = blockIdx.x - 1024;
        const int hg = bid & 7;
        const int qt = (bid >> 3) & 31;
        const int b  = bid >> 8;
        const int head = HL_ + hg;
        const int tok0 = b * S_ + qt * 128;

        const int r2 = tid >> 1, hs = (tid & 1) * 32;
        const uint32_t dst = (uint32_t)(r2 * ATS + hs) * 2;

        {
            const __half* qb = qkv + (size_t)(tok0 + r2) * 3072 + head * 64 + hs;
            #pragma unroll
            for (int i = 0; i < 4; i++) cp16(uQ + dst + i * 16, qb + i * 8);
            const int kidx = r2;
            const int pos = ((kidx >> 5) << 7) + 96 + (kidx & 31);
            const __half* kb = qkv + (size_t)(b * S_ + pos) * 3072 + 1024 + head * 64 + hs;
            #pragma unroll
            for (int i = 0; i < 4; i++) {
                cp16(uK[0] + dst + i * 16, kb + i * 8);
                cp16(uV[0] + dst + i * 16, kb + 1024 + i * 8);
            }
            CP_COMMIT();
        }

        float m0 = -1e30f, m1 = -1e30f, l0 = 0.f, l1 = 0.f;
        float oc[8][4];
        #pragma unroll
        for (int nt = 0; nt < 8; nt++)
            #pragma unroll
            for (int r = 0; r < 4; r++) oc[nt][r] = 0.f;

        for (int t = 0; t < 8; t++) {
            const int buf = t & 1;
            if (t + 1 < 8) {
                const int kidx = (t + 1) * 128 + r2;
                const int pos = ((kidx >> 5) << 7) + 96 + (kidx & 31);
                const __half* kb = qkv + (size_t)(b * S_ + pos) * 3072 + 1024 + head * 64 + hs;
                const int nb = buf ^ 1;
                #pragma unroll
                for (int i = 0; i < 4; i++) {
                    cp16(uK[nb] + dst + i * 16, kb + i * 8);
                    cp16(uV[nb] + dst + i * 16, kb + 1024 + i * 8);
                }
                CP_COMMIT();
                CP_WAIT1();
            } else {
                CP_WAIT0();
            }
            __syncthreads();

            float sc[16][4];
            #pragma unroll
            for (int nt = 0; nt < 16; nt++)
                #pragma unroll
                for (int r = 0; r < 4; r++) sc[nt][r] = 0.f;

            #pragma unroll
            for (int ks = 0; ks < 4; ks++) {
                uint32_t aq[4];
                ldmat_x4(aq[0], aq[1], aq[2], aq[3], uQ + (a_row * ATS + ks * 16 + a_k) * 2);
                #pragma unroll
                for (int p = 0; p < 8; p++) {
                    uint32_t r0, r1, r2b, r3;
                    ldmat_x4(r0, r1, r2b, r3, uK[buf] + ((p * 16 + b_rA) * ATS + ks * 16 + b_k) * 2);
                    mma_f16(sc[2*p][0], sc[2*p][1], sc[2*p][2], sc[2*p][3],
                            aq[0], aq[1], aq[2], aq[3], r0, r1);
                    mma_f16(sc[2*p+1][0], sc[2*p+1][1], sc[2*p+1][2], sc[2*p+1][3],
                            aq[0], aq[1], aq[2], aq[3], r2b, r3);
                }
            }

            float tm0 = -1e30f, tm1 = -1e30f;
            #pragma unroll
            for (int nt = 0; nt < 16; nt++) {
                sc[nt][0] *= SCALE_; sc[nt][1] *= SCALE_;
                sc[nt][2] *= SCALE_; sc[nt][3] *= SCALE_;
                tm0 = fmaxf(tm0, fmaxf(sc[nt][0], sc[nt][1]));
                tm1 = fmaxf(tm1, fmaxf(sc[nt][2], sc[nt][3]));
            }
            tm0 = fmaxf(tm0, __shfl_xor_sync(0xffffffffu, tm0, 1));
            tm0 = fmaxf(tm0, __shfl_xor_sync(0xffffffffu, tm0, 2));
            tm1 = fmaxf(tm1, __shfl_xor_sync(0xffffffffu, tm1, 1));
            tm1 = fmaxf(tm1, __shfl_xor_sync(0xffffffffu, tm1, 2));
            const float mn0 = fmaxf(m0, tm0), mn1 = fmaxf(m1, tm1);
            const float f0 = __expf(m0 - mn0), f1 = __expf(m1 - mn1);
            m0 = mn0; m1 = mn1;

            float ts0 = 0.f, ts1 = 0.f;
            #pragma unroll
            for (int nt = 0; nt < 16; nt++) {
                sc[nt][0] = __expf(sc[nt][0] - mn0); sc[nt][1] = __expf(sc[nt][1] - mn0);
                sc[nt][2] = __expf(sc[nt][2] - mn1); sc[nt][3] = __expf(sc[nt][3] - mn1);
                ts0 += sc[nt][0] + sc[nt][1];
                ts1 += sc[nt][2] + sc[nt][3];
            }
            ts0 += __shfl_xor_sync(0xffffffffu, ts0, 1);
            ts0 += __shfl_xor_sync(0xffffffffu, ts0, 2);
            ts1 += __shfl_xor_sync(0xffffffffu, ts1, 1);
            ts1 += __shfl_xor_sync(0xffffffffu, ts1, 2);
            l0 = l0 * f0 + ts0;
            l1 = l1 * f1 + ts1;

            #pragma unroll
            for (int nt = 0; nt < 8; nt++) {
                oc[nt][0] *= f0; oc[nt][1] *= f0;
                oc[nt][2] *= f1; oc[nt][3] *= f1;
            }

            #pragma unroll
            for (int kk = 0; kk < 8; kk++) {
                uint32_t a0 = packh2(sc[2*kk][0],   sc[2*kk][1]);
                uint32_t a1 = packh2(sc[2*kk][2],   sc[2*kk][3]);
                uint32_t a2 = packh2(sc[2*kk+1][0], sc[2*kk+1][1]);
                uint32_t a3 = packh2(sc[2*kk+1][2], sc[2*kk+1][3]);
                #pragma unroll
                for (int jp = 0; jp < 4; jp++) {
                    uint32_t r0, r1, r2b, r3;
                    ldmat_x4t(r0, r1, r2b, r3, uV[buf] + ((kk * 16 + v_r) * ATS + jp * 16 + v_c) * 2);
                    mma_f16(oc[2*jp][0], oc[2*jp][1], oc[2*jp][2], oc[2*jp][3],
                            a0, a1, a2, a3, r0, r1);
                    mma_f16(oc[2*jp+1][0], oc[2*jp+1][1], oc[2*jp+1][2], oc[2*jp+1][3],
                            a0, a1, a2, a3, r2b, r3);
                }
            }
            __syncthreads();
        }

        const float rl0 = 1.0f / l0, rl1 = 1.0f / l1;
        const int row = tok0 + w * 16 + g;
        __half* op  = out + (size_t)row * 1024 + head * 64;
        __half* op8 = out + (size_t)(row + 8) * 1024 + head * 64;
        #pragma unroll
        for (int nt = 0; nt < 8; nt++) {
            *(__half2*)(op  + nt * 8 + qc * 2) = __floats2half2_rn(oc[nt][0] * rl0, oc[nt][1] * rl0);
            *(__half2*)(op8 + nt * 8 + qc * 2) = __floats2half2_rn(oc[nt][2] * rl1, oc[nt][3] * rl1);
        }
    }
}

// ---------------- fused residual + layernorm -------------------------------------
// XH=1: x is half; XH=0: x is fp32.  y always half.
template<int XH>
__global__ __launch_bounds__(256) void add_ln_kernel(
    const void* __restrict__ xv_, const __half* __restrict__ yh,
    const float* __restrict__ g, const float* __restrict__ bb,
    float* __restrict__ out, __half* __restrict__ out_h)
{
    const int row = blockIdx.x;
    const int tid = threadIdx.x;
    const int lane = tid & 31, warp = tid >> 5;

    float4 xv;
    if (XH) {
        const __half2* x2 = (const __half2*)xv_;
        float2 x01 = __half22float2(x2[(size_t)row * 512 + tid * 2]);
        float2 x23 = __half22float2(x2[(size_t)row * 512 + tid * 2 + 1]);
        xv = make_float4(x01.x, x01.y, x23.x, x23.y);
    } else {
        xv = ((const float4*)xv_)[(size_t)row * 256 + tid];
    }
    const __half2* y2 = (const __half2*)yh;
    float2 y01 = __half22float2(y2[(size_t)row * 512 + tid * 2]);
    float2 y23 = __half22float2(y2[(size_t)row * 512 + tid * 2 + 1]);
    float4 vval;
    vval.x = xv.x + y01.x; vval.y = xv.y + y01.y;
    vval.z = xv.z + y23.x; vval.w = xv.w + y23.y;

    float s  = vval.x + vval.y + vval.z + vval.w;
    float sq = vval.x * vval.x + vval.y * vval.y + vval.z * vval.z + vval.w * vval.w;
    #pragma unroll
    for (int o = 16; o; o >>= 1) {
        s  += __shfl_xor_sync(0xffffffffu, s, o);
        sq += __shfl_xor_sync(0xffffffffu, sq, o);
    }
    __shared__ float ws[8], wq[8];
    __shared__ float mu_s, rstd_s;
    if (lane == 0) { ws[warp] = s; wq[warp] = sq; }
    __syncthreads();
    if (warp == 0) {
        float a  = (lane < 8) ? ws[lane] : 0.f;
        float b2 = (lane < 8) ? wq[lane] : 0.f;
        #pragma unroll
        for (int o = 4; o; o >>= 1) {
            a  += __shfl_xor_sync(0xffffffffu, a, o);
            b2 += __shfl_xor_sync(0xffffffffu, b2, o);
        }
        if (lane == 0) {
            float mu = a * (1.0f / 1024.0f);
            float var = b2 * (1.0f / 1024.0f) - mu * mu;
            mu_s = mu;
            rstd_s = rsqrtf(var + 1e-6f);
        }
    }
    __syncthreads();
    float mu = mu_s, rstd = rstd_s;

    float4 gv = ((const float4*)g)[tid];
    float4 bv = ((const float4*)bb)[tid];
    float4 r;
    r.x = gv.x * (vval.x - mu) * rstd + bv.x;
    r.y = gv.y * (vval.y - mu) * rstd + bv.y;
    r.z = gv.z * (vval.z - mu) * rstd + bv.z;
    r.w = gv.w * (vval.w - mu) * rstd + bv.w;
    ((float4*)out)[(size_t)row * 256 + tid] = r;
    if (out_h) {
        __half2* oh = (__half2*)out_h;
        oh[(size_t)row * 512 + tid * 2]     = __floats2half2_rn(r.x, r.y);
        oh[(size_t)row * 512 + tid * 2 + 1] = __floats2half2_rn(r.z, r.w);
    }
}

// ---------------- launcher ---------------------------------------------------------
extern "C" void kernel_launch(void* const* d_in, const int* in_sizes, int n_in,
                              void* d_out, int out_size)
{
    const float* src  = (const float*)d_in[0];
    const float* Wq   = (const float*)d_in[2];
    const float* bq   = (const float*)d_in[3];
    const float* Wk   = (const float*)d_in[4];
    const float* bk   = (const float*)d_in[5];
    const float* Wv   = (const float*)d_in[6];
    const float* bv   = (const float*)d_in[7];
    const float* Wo   = (const float*)d_in[8];
    const float* bo   = (const float*)d_in[9];
    const float* ln1g = (const float*)d_in[10];
    const float* ln1b = (const float*)d_in[11];
    const float* W1   = (const float*)d_in[12];
    const float* b1   = (const float*)d_in[13];
    const float* W2   = (const float*)d_in[14];
    const float* b2   = (const float*)d_in[15];
    const float* ln2g = (const float*)d_in[16];
    const float* ln2b = (const float*)d_in[17];
    float* out = (float*)d_out;

    float *attn, *bqkv;
    __half *qkvh, *hx, *hao, *hattn, *hh, *wh;
    cudaGetSymbolAddress((void**)&qkvh,  g_qkvh);
    cudaGetSymbolAddress((void**)&attn,  g_attn);
    cudaGetSymbolAddress((void**)&bqkv,  g_bqkv);
    cudaGetSymbolAddress((void**)&hx,    g_hx);
    cudaGetSymbolAddress((void**)&hao,   g_hao);
    cudaGetSymbolAddress((void**)&hattn, g_hattn);
    cudaGetSymbolAddress((void**)&hh,    g_hh);
    cudaGetSymbolAddress((void**)&wh,    g_wh);

    __half* proj_h = hh;     // reuse: hh free until FFN1 (which runs after LN1 consumes proj)
    __half* f2_h   = qkvh;   // reuse: qkvh dead after attention

    cudaFuncSetAttribute(attn_mma,        cudaFuncAttributeMaxDynamicSharedMemorySize, SMEM_ATT);
    cudaFuncSetAttribute(hgemm_kernel<0>, cudaFuncAttributeMaxDynamicSharedMemorySize, SMEM_GEMM);
    cudaFuncSetAttribute(hgemm_kernel<1>, cudaFuncAttributeMaxDynamicSharedMemorySize, SMEM_GEMM);
    cudaFuncSetAttribute(hgemm_kernel<2>, cudaFuncAttributeMaxDynamicSharedMemorySize, SMEM_GEMM);

    // #1: all prep (src f2h + weight transposes + bias pack)
    prep_kernel<<<28673, 256>>>(src, hx, Wq, Wk, Wv, Wo, W1, W2, bq, bk, bv, wh, bqkv);

    // #2: fused QKV projection -> half [M,3072]
    hgemm_kernel<2><<<dim3(24, 128), 256, SMEM_GEMM>>>(hx, wh + WQKV_OFF, bqkv, qkvh, M_, 3072, D_);

    // #3: fused tensor-core sparse attention -> hao (half)
    attn_mma<<<2048, 256, SMEM_ATT>>>(qkvh, hao);

    // #4: output projection -> half (into hh region; hx stays alive)
    hgemm_kernel<2><<<dim3(8, 128), 256, SMEM_GEMM>>>(hao, wh + WO_OFF, bo, proj_h, M_, D_, D_);

    // #5: attn = LN1(src_h + proj); half copy for FFN1 (x read in half)
    add_ln_kernel<1><<<M_, 256>>>(hx, proj_h, ln1g, ln1b, attn, hattn);

    // #6,#7: FFN (FFN1 overwrites hh with the hidden activations)
    hgemm_kernel<1><<<dim3(32, 128), 256, SMEM_GEMM>>>(hattn, wh + W1_OFF, b1, hh, M_, DFF_, D_);
    hgemm_kernel<2><<<dim3(8, 128), 256, SMEM_GEMM>>>(hh, wh + W2_OFF, b2, f2_h, M_, D_, DFF_);

    // #8: out = LN2(attn + ffn)  (x = attn fp32 for precision)
    add_ln_kernel<0><<<M_, 256>>>(attn, f2_h, ln2g, ln2b, out, nullptr);
}

// round 15
// speedup vs baseline: 1.1621x; 1.0077x over previous
#include <cuda_runtime.h>
#include <cuda_fp16.h>
#include <math.h>
#include <stdint.h>

#define D_ 1024
#define H_ 16
#define HD_ 64
#define HL_ 8
#define STRIDE_ 128
#define DFF_ 4096
#define B_ 4
#define S_ 4096
#define M_ (B_*S_)
#define NB_ (S_/STRIDE_)
#define SCALE_ 0.125f

// ---------------- scratch (device globals; no allocation allowed) ----------------
__device__ __half g_qkvh[(size_t)M_ * 3072];   // reused as f2 (half) after attention
__device__ float  g_bqkv[3072];
__device__ __half g_hx[M_ * D_];               // src half (alive through LN1)
__device__ __half g_hao[M_ * D_];
__device__ __half g_hattn[M_ * D_];            // LN1 out (FFN1 input + LN2 residual)
__device__ __half g_hh[(size_t)M_ * DFF_];     // proj (half) before FFN1 overwrites with hidden
__device__ __half g_wh[12 * 1024 * 1024 + 1024 * 1024];  // packed half weights

#define WQKV_OFF 0                      // [3072][1024]
#define WO_OFF   (3072*1024)            // [1024][1024]
#define W1_OFF   (4096*1024)            // [4096][1024]
#define W2_OFF   (8192*1024)            // [1024][4096]

// ============================ helpers =============================================
__device__ __forceinline__ uint32_t smem_u32(const void* p) {
    uint32_t a;
    asm("{ .reg .u64 t; cvta.to.shared.u64 t, %1; cvt.u32.u64 %0, t; }" : "=r"(a) : "l"(p));
    return a;
}
__device__ __forceinline__ void cp16(uint32_t dst, const void* src) {
    asm volatile("cp.async.cg.shared.global [%0], [%1], 16;" :: "r"(dst), "l"(src));
}
#define CP_COMMIT()  asm volatile("cp.async.commit_group;" ::: "memory")
#define CP_WAIT2()   asm volatile("cp.async.wait_group 2;" ::: "memory")
#define CP_WAIT1()   asm volatile("cp.async.wait_group 1;" ::: "memory")
#define CP_WAIT0()   asm volatile("cp.async.wait_group 0;" ::: "memory")

__device__ __forceinline__ void ldmat_x4(uint32_t& r0, uint32_t& r1, uint32_t& r2, uint32_t& r3,
                                         uint32_t addr) {
    asm volatile("ldmatrix.sync.aligned.m8n8.x4.shared.b16 {%0,%1,%2,%3}, [%4];"
        : "=r"(r0), "=r"(r1), "=r"(r2), "=r"(r3) : "r"(addr));
}
__device__ __forceinline__ void ldmat_x4t(uint32_t& r0, uint32_t& r1, uint32_t& r2, uint32_t& r3,
                                          uint32_t addr) {
    asm volatile("ldmatrix.sync.aligned.m8n8.x4.trans.shared.b16 {%0,%1,%2,%3}, [%4];"
        : "=r"(r0), "=r"(r1), "=r"(r2), "=r"(r3) : "r"(addr));
}
__device__ __forceinline__ void mma_f16(float& c0, float& c1, float& c2, float& c3,
                                        uint32_t a0, uint32_t a1, uint32_t a2, uint32_t a3,
                                        uint32_t b0, uint32_t b1) {
    asm volatile(
        "mma.sync.aligned.m16n8k16.row.col.f32.f16.f16.f32 "
        "{%0,%1,%2,%3}, {%4,%5,%6,%7}, {%8,%9}, {%0,%1,%2,%3};"
        : "+f"(c0), "+f"(c1), "+f"(c2), "+f"(c3)
        : "r"(a0), "r"(a1), "r"(a2), "r"(a3), "r"(b0), "r"(b1));
}
__device__ __forceinline__ uint32_t packh2(float x, float y) {
    __half2 h = __floats2half2_rn(x, y);
    return *(uint32_t*)&h;
}

// ============================ fp16 mma.sync GEMM (R11 verified config) ============
#define BKH 32
#define BSTR 40
#define ASTG (128 * BSTR)
#define STG  (2 * ASTG)
#define NSTAGE 4
#define SMEM_GEMM (NSTAGE * STG * 2)     // 81920 bytes

template<int MODE>
__global__ __launch_bounds__(256, 2) void hgemm_kernel(
    const __half* __restrict__ A, const __half* __restrict__ BT,
    const float* __restrict__ bias, void* __restrict__ Cv,
    int M, int N, int K)
{
    extern __shared__ __half smh[];
    const uint32_t sbase = smem_u32(smh);

    const int tid = threadIdx.x;
    const int wid = tid >> 5, lane = tid & 31;
    const int g = lane >> 2, qc = lane & 3;
    const int n0 = blockIdx.x * 128, m0 = blockIdx.y * 128;
    const int warpM = wid & 1, warpN = wid >> 1;

    const int row2 = tid >> 1;
    const int hc = (tid & 1) * 16;
    const __half* Ag = A  + (size_t)(m0 + row2) * K + hc;
    const __half* Bg = BT + (size_t)(n0 + row2) * K + hc;
    const uint32_t soff = (uint32_t)(row2 * BSTR + hc) * 2;

    const int nch = K / BKH;

    #pragma unroll
    for (int pc = 0; pc < NSTAGE - 1; pc++) {
        const uint32_t sa = sbase + pc * (STG * 2);
        const uint32_t sb = sa + ASTG * 2;
        const __half* Ap = Ag + pc * BKH;
        const __half* Bp = Bg + pc * BKH;
        cp16(sa + soff,      Ap);
        cp16(sa + soff + 16, Ap + 8);
        cp16(sb + soff,      Bp);
        cp16(sb + soff + 16, Bp + 8);
        CP_COMMIT();
    }

    float cfr[4][4][4];
    #pragma unroll
    for (int mt = 0; mt < 4; mt++)
        #pragma unroll
        for (int nt = 0; nt < 4; nt++)
            #pragma unroll
            for (int r = 0; r < 4; r++) cfr[mt][nt][r] = 0.f;

    const uint32_t a_lrow = (uint32_t)(warpM * 64 + (lane & 15));
    const uint32_t a_kofs = (uint32_t)((lane >> 4) << 3);
    const uint32_t b_lrow = (uint32_t)(warpN * 32 + ((lane >> 4) << 3) + (lane & 7));
    const uint32_t b_kofs = (uint32_t)(((lane >> 3) & 1) << 3);

    for (int c = 0; c < nch; c++) {
        const int stg = c & (NSTAGE - 1);
        const uint32_t sa = sbase + stg * (STG * 2);
        const uint32_t sb = sa + ASTG * 2;

        CP_WAIT2();
        __syncthreads();

        #pragma unroll
        for (int ks = 0; ks < 2; ks++) {
            uint32_t af[4][4];
            #pragma unroll
            for (int mt = 0; mt < 4; mt++) {
                uint32_t addr = sa + ((a_lrow + mt * 16) * BSTR + ks * 16 + a_kofs) * 2;
                ldmat_x4(af[mt][0], af[mt][1], af[mt][2], af[mt][3], addr);
            }
            uint32_t bf[4][2];
            #pragma unroll
            for (int p = 0; p < 2; p++) {
                uint32_t addr = sb + ((b_lrow + p * 16) * BSTR + ks * 16 + b_kofs) * 2;
                ldmat_x4(bf[2 * p][0], bf[2 * p][1], bf[2 * p + 1][0], bf[2 * p + 1][1], addr);
            }
            #pragma unroll
            for (int mt = 0; mt < 4; mt++)
                #pragma unroll
                for (int nt = 0; nt < 4; nt++)
                    mma_f16(cfr[mt][nt][0], cfr[mt][nt][1], cfr[mt][nt][2], cfr[mt][nt][3],
                            af[mt][0], af[mt][1], af[mt][2], af[mt][3],
                            bf[nt][0], bf[nt][1]);
        }

        const int pc = c + NSTAGE - 1;
        if (pc < nch) {
            const int ps = pc & (NSTAGE - 1);
            const uint32_t pa = sbase + ps * (STG * 2);
            const uint32_t pb = pa + ASTG * 2;
            const __half* Ap = Ag + (size_t)pc * BKH;
            const __half* Bp = Bg + (size_t)pc * BKH;
            cp16(pa + soff,      Ap);
            cp16(pa + soff + 16, Ap + 8);
            cp16(pb + soff,      Bp);
            cp16(pb + soff + 16, Bp + 8);
        }
        CP_COMMIT();
    }

    #pragma unroll
    for (int mt = 0; mt < 4; mt++) {
        const int row = m0 + warpM * 64 + mt * 16 + g;
        #pragma unroll
        for (int nt = 0; nt < 4; nt++) {
            const int col = n0 + warpN * 32 + nt * 8 + qc * 2;
            float b0 = __ldg(&bias[col]), b1 = __ldg(&bias[col + 1]);
            float v0 = cfr[mt][nt][0] + b0, v1 = cfr[mt][nt][1] + b1;
            float v2 = cfr[mt][nt][2] + b0, v3 = cfr[mt][nt][3] + b1;
            if (MODE == 0) {
                float* Cf = (float*)Cv;
                *(float2*)&Cf[(size_t)row * N + col]       = make_float2(v0, v1);
                *(float2*)&Cf[(size_t)(row + 8) * N + col] = make_float2(v2, v3);
            } else {
                __half* Ch = (__half*)Cv;
                if (MODE == 1) {
                    v0 = fmaxf(v0, 0.f); v1 = fmaxf(v1, 0.f);
                    v2 = fmaxf(v2, 0.f); v3 = fmaxf(v3, 0.f);
                }
                *(__half2*)&Ch[(size_t)row * N + col]       = __floats2half2_rn(v0, v1);
                *(__half2*)&Ch[(size_t)(row + 8) * N + col] = __floats2half2_rn(v2, v3);
            }
        }
    }
}

// ---------------- merged prep: src f2h + 6 weight transposes + bias pack -----------
__global__ __launch_bounds__(256) void prep_kernel(
    const float* __restrict__ src, __half* __restrict__ hx,
    const float* __restrict__ Wq, const float* __restrict__ Wk,
    const float* __restrict__ Wv, const float* __restrict__ Wo,
    const float* __restrict__ W1, const float* __restrict__ W2,
    const float* __restrict__ bq, const float* __restrict__ bk,
    const float* __restrict__ bv,
    __half* __restrict__ wh, float* __restrict__ bqkv)
{
    const int id = blockIdx.x;
    if (id < 16384) {
        const int i = id * 256 + threadIdx.x;
        float4 v = ((const float4*)src)[i];
        __half2* o = (__half2*)hx;
        o[i * 2]     = __floats2half2_rn(v.x, v.y);
        o[i * 2 + 1] = __floats2half2_rn(v.z, v.w);
        return;
    }
    if (id == 28672) {
        for (int j = threadIdx.x; j < 3072; j += 256)
            bqkv[j] = (j < 1024) ? bq[j] : (j < 2048) ? bk[j - 1024] : bv[j - 2048];
        return;
    }

    const int tidb = id - 16384;
    const float* in;
    __half* outp;
    int K, N, bx, by;
    if (tidb < 4096) {
        const int m = tidb >> 10, lid = tidb & 1023;
        in   = (m == 0) ? Wq : (m == 1) ? Wk : (m == 2) ? Wv : Wo;
        outp = wh + ((m == 3) ? WO_OFF : WQKV_OFF + m * 1024 * 1024);
        K = 1024; N = 1024; bx = lid & 31; by = lid >> 5;
    } else if (tidb < 8192) {
        const int lid = tidb - 4096;
        in = W1; outp = wh + W1_OFF;
        K = 1024; N = 4096; bx = lid & 127; by = lid >> 7;
    } else {
        const int lid = tidb - 8192;
        in = W2; outp = wh + W2_OFF;
        K = 4096; N = 1024; bx = lid & 31; by = lid >> 5;
    }

    __shared__ float t[32][33];
    const int n0 = bx * 32, k0 = by * 32;
    const int tx = threadIdx.x & 31, ty = threadIdx.x >> 5;
    #pragma unroll
    for (int i = 0; i < 4; i++)
        t[ty + i * 8][tx] = in[(size_t)(k0 + ty + i * 8) * N + n0 + tx];
    __syncthreads();
    #pragma unroll
    for (int i = 0; i < 4; i++)
        outp[(size_t)(n0 + ty + i * 8) * K + k0 + tx] = __float2half(t[tx][ty + i * 8]);
}

// ============================ fused tensor-core attention =========================
#define ATS 72
#define SMEM_ATT (5 * 128 * ATS * 2)   // 92160

__global__ __launch_bounds__(256, 2) void attn_mma(
    const __half* __restrict__ qkv, __half* __restrict__ out)
{
    extern __shared__ __half sm[];
    const int tid = threadIdx.x;
    const int w = tid >> 5, lane = tid & 31;
    const int g = lane >> 2, qc = lane & 3;

    const uint32_t a_row = (uint32_t)(w * 16 + (lane & 15));
    const uint32_t a_k   = (uint32_t)((lane >> 4) << 3);
    const uint32_t b_rA  = (uint32_t)(((lane >> 4) << 3) + (lane & 7));
    const uint32_t b_k   = (uint32_t)(((lane >> 3) & 1) << 3);
    const uint32_t v_r   = (uint32_t)(lane & 15);
    const uint32_t v_c   = (uint32_t)((lane >> 4) << 3);

    if (blockIdx.x < 1024) {
        __half* sQ = sm;
        __half* sK = sm + 128 * ATS;
        __half* sV = sm + 2 * 128 * ATS;
        const uint32_t uQ = smem_u32(sQ), uK = smem_u32(sK), uV = smem_u32(sV);

        const int bid = blockIdx.x;
        const int h = bid % HL_;
        const int n = (bid / HL_) % NB_;
        const int b = bid / (HL_ * NB_);
        const int tok0 = b * S_ + n * STRIDE_;

        {
            const int r2 = tid >> 1, hs = (tid & 1) * 32;
            const __half* base = qkv + (size_t)(tok0 + r2) * 3072 + h * 64 + hs;
            const uint32_t dst = (uint32_t)(r2 * ATS + hs) * 2;
            #pragma unroll
            for (int i = 0; i < 4; i++) {
                cp16(uQ + dst + i * 16, base + i * 8);
                cp16(uK + dst + i * 16, base + 1024 + i * 8);
                cp16(uV + dst + i * 16, base + 2048 + i * 8);
            }
            CP_COMMIT();
        }
        CP_WAIT0();
        __syncthreads();

        float sc[16][4];
        #pragma unroll
        for (int nt = 0; nt < 16; nt++)
            #pragma unroll
            for (int r = 0; r < 4; r++) sc[nt][r] = 0.f;

        #pragma unroll
        for (int ks = 0; ks < 4; ks++) {
            uint32_t aq[4];
            ldmat_x4(aq[0], aq[1], aq[2], aq[3], uQ + (a_row * ATS + ks * 16 + a_k) * 2);
            #pragma unroll
            for (int p = 0; p < 8; p++) {
                uint32_t r0, r1, r2, r3;
                ldmat_x4(r0, r1, r2, r3, uK + ((p * 16 + b_rA) * ATS + ks * 16 + b_k) * 2);
                mma_f16(sc[2*p][0], sc[2*p][1], sc[2*p][2], sc[2*p][3],
                        aq[0], aq[1], aq[2], aq[3], r0, r1);
                mma_f16(sc[2*p+1][0], sc[2*p+1][1], sc[2*p+1][2], sc[2*p+1][3],
                        aq[0], aq[1], aq[2], aq[3], r2, r3);
            }
        }

        float m0 = -1e30f, m1 = -1e30f;
        #pragma unroll
        for (int nt = 0; nt < 16; nt++) {
            sc[nt][0] *= SCALE_; sc[nt][1] *= SCALE_;
            sc[nt][2] *= SCALE_; sc[nt][3] *= SCALE_;
            m0 = fmaxf(m0, fmaxf(sc[nt][0], sc[nt][1]));
            m1 = fmaxf(m1, fmaxf(sc[nt][2], sc[nt][3]));
        }
        m0 = fmaxf(m0, __shfl_xor_sync(0xffffffffu, m0, 1));
        m0 = fmaxf(m0, __shfl_xor_sync(0xffffffffu, m0, 2));
        m1 = fmaxf(m1, __shfl_xor_sync(0xffffffffu, m1, 1));
        m1 = fmaxf(m1, __shfl_xor_sync(0xffffffffu, m1, 2));
        float l0 = 0.f, l1 = 0.f;
        #pragma unroll
        for (int nt = 0; nt < 16; nt++) {
            sc[nt][0] = __expf(sc[nt][0] - m0); sc[nt][1] = __expf(sc[nt][1] - m0);
            sc[nt][2] = __expf(sc[nt][2] - m1); sc[nt][3] = __expf(sc[nt][3] - m1);
            l0 += sc[nt][0] + sc[nt][1];
            l1 += sc[nt][2] + sc[nt][3];
        }
        l0 += __shfl_xor_sync(0xffffffffu, l0, 1);
        l0 += __shfl_xor_sync(0xffffffffu, l0, 2);
        l1 += __shfl_xor_sync(0xffffffffu, l1, 1);
        l1 += __shfl_xor_sync(0xffffffffu, l1, 2);
        const float rl0 = 1.0f / l0, rl1 = 1.0f / l1;
        #pragma unroll
        for (int nt = 0; nt < 16; nt++) {
            sc[nt][0] *= rl0; sc[nt][1] *= rl0;
            sc[nt][2] *= rl1; sc[nt][3] *= rl1;
        }

        float oc[8][4];
        #pragma unroll
        for (int nt = 0; nt < 8; nt++)
            #pragma unroll
            for (int r = 0; r < 4; r++) oc[nt][r] = 0.f;

        #pragma unroll
        for (int kk = 0; kk < 8; kk++) {
            uint32_t a0 = packh2(sc[2*kk][0],   sc[2*kk][1]);
            uint32_t a1 = packh2(sc[2*kk][2],   sc[2*kk][3]);
            uint32_t a2 = packh2(sc[2*kk+1][0], sc[2*kk+1][1]);
            uint32_t a3 = packh2(sc[2*kk+1][2], sc[2*kk+1][3]);
            #pragma unroll
            for (int jp = 0; jp < 4; jp++) {
                uint32_t r0, r1, r2, r3;
                ldmat_x4t(r0, r1, r2, r3, uV + ((kk * 16 + v_r) * ATS + jp * 16 + v_c) * 2);
                mma_f16(oc[2*jp][0], oc[2*jp][1], oc[2*jp][2], oc[2*jp][3],
                        a0, a1, a2, a3, r0, r1);
                mma_f16(oc[2*jp+1][0], oc[2*jp+1][1], oc[2*jp+1][2], oc[2*jp+1][3],
                        a0, a1, a2, a3, r2, r3);
            }
        }

        const int row = tok0 + w * 16 + g;
        __half* op  = out + (size_t)row * 1024 + h * 64;
        __half* op8 = out + (size_t)(row + 8) * 1024 + h * 64;
        #pragma unroll
        for (int nt = 0; nt < 8; nt++) {
            *(__half2*)(op  + nt * 8 + qc * 2) = __floats2half2_rn(oc[nt][0], oc[nt][1]);
            *(__half2*)(op8 + nt * 8 + qc * 2) = __floats2half2_rn(oc[nt][2], oc[nt][3]);
        }
    } else {
        __half* sQ = sm;
        __half* sK0 = sm + 128 * ATS;
        __half* sV0 = sm + 3 * 128 * ATS;
        const uint32_t uQ = smem_u32(sQ);
        const uint32_t uK[2] = { smem_u32(sK0), smem_u32(sK0 + 128 * ATS) };
        const uint32_t uV[2] = { smem_u32(sV0), smem_u32(sV0 + 128 * ATS) };

        const int bid = blockIdx.x - 1024;
        const int hg = bid & 7;
        const int qt = (bid >> 3) & 31;
        const int b  = bid >> 8;
        const int head = HL_ + hg;
        const int tok0 = b * S_ + qt * 128;

        const int r2 = tid >> 1, hs = (tid & 1) * 32;
        const uint32_t dst = (uint32_t)(r2 * ATS + hs) * 2;

        {
            const __half* qb = qkv + (size_t)(tok0 + r2) * 3072 + head * 64 + hs;
            #pragma unroll
            for (int i = 0; i < 4; i++) cp16(uQ + dst + i * 16, qb + i * 8);
            const int kidx = r2;
            const int pos = ((kidx >> 5) << 7) + 96 + (kidx & 31);
            const __half* kb = qkv + (size_t)(b * S_ + pos) * 3072 + 1024 + head * 64 + hs;
            #pragma unroll
            for (int i = 0; i < 4; i++) {
                cp16(uK[0] + dst + i * 16, kb + i * 8);
                cp16(uV[0] + dst + i * 16, kb + 1024 + i * 8);
            }
            CP_COMMIT();
        }

        float m0 = -1e30f, m1 = -1e30f, l0 = 0.f, l1 = 0.f;
        float oc[8][4];
        #pragma unroll
        for (int nt = 0; nt < 8; nt++)
            #pragma unroll
            for (int r = 0; r < 4; r++) oc[nt][r] = 0.f;

        for (int t = 0; t < 8; t++) {
            const int buf = t & 1;
            if (t + 1 < 8) {
                const int kidx = (t + 1) * 128 + r2;
                const int pos = ((kidx >> 5) << 7) + 96 + (kidx & 31);
                const __half* kb = qkv + (size_t)(b * S_ + pos) * 3072 + 1024 + head * 64 + hs;
                const int nb = buf ^ 1;
                #pragma unroll
                for (int i = 0; i < 4; i++) {
                    cp16(uK[nb] + dst + i * 16, kb + i * 8);
                    cp16(uV[nb] + dst + i * 16, kb + 1024 + i * 8);
                }
                CP_COMMIT();
                CP_WAIT1();
            } else {
                CP_WAIT0();
            }
            __syncthreads();

            float sc[16][4];
            #pragma unroll
            for (int nt = 0; nt < 16; nt++)
                #pragma unroll
                for (int r = 0; r < 4; r++) sc[nt][r] = 0.f;

            #pragma unroll
            for (int ks = 0; ks < 4; ks++) {
                uint32_t aq[4];
                ldmat_x4(aq[0], aq[1], aq[2], aq[3], uQ + (a_row * ATS + ks * 16 + a_k) * 2);
                #pragma unroll
                for (int p = 0; p < 8; p++) {
                    uint32_t r0, r1, r2b, r3;
                    ldmat_x4(r0, r1, r2b, r3, uK[buf] + ((p * 16 + b_rA) * ATS + ks * 16 + b_k) * 2);
                    mma_f16(sc[2*p][0], sc[2*p][1], sc[2*p][2], sc[2*p][3],
                            aq[0], aq[1], aq[2], aq[3], r0, r1);
                    mma_f16(sc[2*p+1][0], sc[2*p+1][1], sc[2*p+1][2], sc[2*p+1][3],
                            aq[0], aq[1], aq[2], aq[3], r2b, r3);
                }
            }

            float tm0 = -1e30f, tm1 = -1e30f;
            #pragma unroll
            for (int nt = 0; nt < 16; nt++) {
                sc[nt][0] *= SCALE_; sc[nt][1] *= SCALE_;
                sc[nt][2] *= SCALE_; sc[nt][3] *= SCALE_;
                tm0 = fmaxf(tm0, fmaxf(sc[nt][0], sc[nt][1]));
                tm1 = fmaxf(tm1, fmaxf(sc[nt][2], sc[nt][3]));
            }
            tm0 = fmaxf(tm0, __shfl_xor_sync(0xffffffffu, tm0, 1));
            tm0 = fmaxf(tm0, __shfl_xor_sync(0xffffffffu, tm0, 2));
            tm1 = fmaxf(tm1, __shfl_xor_sync(0xffffffffu, tm1, 1));
            tm1 = fmaxf(tm1, __shfl_xor_sync(0xffffffffu, tm1, 2));
            const float mn0 = fmaxf(m0, tm0), mn1 = fmaxf(m1, tm1);
            const float f0 = __expf(m0 - mn0), f1 = __expf(m1 - mn1);
            m0 = mn0; m1 = mn1;

            float ts0 = 0.f, ts1 = 0.f;
            #pragma unroll
            for (int nt = 0; nt < 16; nt++) {
                sc[nt][0] = __expf(sc[nt][0] - mn0); sc[nt][1] = __expf(sc[nt][1] - mn0);
                sc[nt][2] = __expf(sc[nt][2] - mn1); sc[nt][3] = __expf(sc[nt][3] - mn1);
                ts0 += sc[nt][0] + sc[nt][1];
                ts1 += sc[nt][2] + sc[nt][3];
            }
            ts0 += __shfl_xor_sync(0xffffffffu, ts0, 1);
            ts0 += __shfl_xor_sync(0xffffffffu, ts0, 2);
            ts1 += __shfl_xor_sync(0xffffffffu, ts1, 1);
            ts1 += __shfl_xor_sync(0xffffffffu, ts1, 2);
            l0 = l0 * f0 + ts0;
            l1 = l1 * f1 + ts1;

            #pragma unroll
            for (int nt = 0; nt < 8; nt++) {
                oc[nt][0] *= f0; oc[nt][1] *= f0;
                oc[nt][2] *= f1; oc[nt][3] *= f1;
            }

            #pragma unroll
            for (int kk = 0; kk < 8; kk++) {
                uint32_t a0 = packh2(sc[2*kk][0],   sc[2*kk][1]);
                uint32_t a1 = packh2(sc[2*kk][2],   sc[2*kk][3]);
                uint32_t a2 = packh2(sc[2*kk+1][0], sc[2*kk+1][1]);
                uint32_t a3 = packh2(sc[2*kk+1][2], sc[2*kk+1][3]);
                #pragma unroll
                for (int jp = 0; jp < 4; jp++) {
                    uint32_t r0, r1, r2b, r3;
                    ldmat_x4t(r0, r1, r2b, r3, uV[buf] + ((kk * 16 + v_r) * ATS + jp * 16 + v_c) * 2);
                    mma_f16(oc[2*jp][0], oc[2*jp][1], oc[2*jp][2], oc[2*jp][3],
                            a0, a1, a2, a3, r0, r1);
                    mma_f16(oc[2*jp+1][0], oc[2*jp+1][1], oc[2*jp+1][2], oc[2*jp+1][3],
                            a0, a1, a2, a3, r2b, r3);
                }
            }
            __syncthreads();
        }

        const float rl0 = 1.0f / l0, rl1 = 1.0f / l1;
        const int row = tok0 + w * 16 + g;
        __half* op  = out + (size_t)row * 1024 + head * 64;
        __half* op8 = out + (size_t)(row + 8) * 1024 + head * 64;
        #pragma unroll
        for (int nt = 0; nt < 8; nt++) {
            *(__half2*)(op  + nt * 8 + qc * 2) = __floats2half2_rn(oc[nt][0] * rl0, oc[nt][1] * rl0);
            *(__half2*)(op8 + nt * 8 + qc * 2) = __floats2half2_rn(oc[nt][2] * rl1, oc[nt][3] * rl1);
        }
    }
}

// ---------------- warp-per-row residual + layernorm (both inputs half) -------------
// OUTF=1: write fp32 out.  OUTF=0: write half out.
// Grid: M_/8 blocks x 256 threads; warp w handles row blockIdx.x*8 + w.
template<int OUTF>
__global__ __launch_bounds__(256) void add_ln_w_kernel(
    const __half* __restrict__ xh, const __half* __restrict__ yh,
    const float* __restrict__ g, const float* __restrict__ bb,
    float* __restrict__ outf, __half* __restrict__ outh)
{
    const int warp = threadIdx.x >> 5, lane = threadIdx.x & 31;
    const int row = blockIdx.x * 8 + warp;
    const uint4* x4 = (const uint4*)(xh + (size_t)row * 1024);
    const uint4* y4 = (const uint4*)(yh + (size_t)row * 1024);

    float v[32];
    float s = 0.f, sq = 0.f;
    #pragma unroll
    for (int i = 0; i < 4; i++) {
        uint4 xv = x4[lane + 32 * i];
        uint4 yv = y4[lane + 32 * i];
        const uint32_t* xw = (const uint32_t*)&xv;
        const uint32_t* yw = (const uint32_t*)&yv;
        #pragma unroll
        for (int k = 0; k < 4; k++) {
            float2 xf = __half22float2(*(__half2*)&xw[k]);
            float2 yf = __half22float2(*(__half2*)&yw[k]);
            float a = xf.x + yf.x, b = xf.y + yf.y;
            v[i * 8 + k * 2]     = a;
            v[i * 8 + k * 2 + 1] = b;
            s += a + b;
            sq += a * a + b * b;
        }
    }
    #pragma unroll
    for (int o = 16; o; o >>= 1) {
        s  += __shfl_xor_sync(0xffffffffu, s, o);
        sq += __shfl_xor_sync(0xffffffffu, sq, o);
    }
    const float mu = s * (1.0f / 1024.0f);
    const float rstd = rsqrtf(sq * (1.0f / 1024.0f) - mu * mu + 1e-6f);

    #pragma unroll
    for (int i = 0; i < 4; i++) {
        const int c8 = (lane + 32 * i) * 2;     // float4 pair base (covers 8 cols)
        float4 g0 = ((const float4*)g)[c8],  g1 = ((const float4*)g)[c8 + 1];
        float4 b0 = ((const float4*)bb)[c8], b1 = ((const float4*)bb)[c8 + 1];
        float r0 = g0.x * (v[i*8+0] - mu) * rstd + b0.x;
        float r1 = g0.y * (v[i*8+1] - mu) * rstd + b0.y;
        float r2 = g0.z * (v[i*8+2] - mu) * rstd + b0.z;
        float r3 = g0.w * (v[i*8+3] - mu) * rstd + b0.w;
        float r4 = g1.x * (v[i*8+4] - mu) * rstd + b1.x;
        float r5 = g1.y * (v[i*8+5] - mu) * rstd + b1.y;
        float r6 = g1.z * (v[i*8+6] - mu) * rstd + b1.z;
        float r7 = g1.w * (v[i*8+7] - mu) * rstd + b1.w;
        if (OUTF) {
            float4* o4 = (float4*)(outf + (size_t)row * 1024);
            o4[c8]     = make_float4(r0, r1, r2, r3);
            o4[c8 + 1] = make_float4(r4, r5, r6, r7);
        } else {
            uint4 ov;
            uint32_t* ow = (uint32_t*)&ov;
            ow[0] = packh2(r0, r1); ow[1] = packh2(r2, r3);
            ow[2] = packh2(r4, r5); ow[3] = packh2(r6, r7);
            ((uint4*)(outh + (size_t)row * 1024))[lane + 32 * i] = ov;
        }
    }
}

// ---------------- launcher ---------------------------------------------------------
extern "C" void kernel_launch(void* const* d_in, const int* in_sizes, int n_in,
                              void* d_out, int out_size)
{
    const float* src  = (const float*)d_in[0];
    const float* Wq   = (const float*)d_in[2];
    const float* bq   = (const float*)d_in[3];
    const float* Wk   = (const float*)d_in[4];
    const float* bk   = (const float*)d_in[5];
    const float* Wv   = (const float*)d_in[6];
    const float* bv   = (const float*)d_in[7];
    const float* Wo   = (const float*)d_in[8];
    const float* bo   = (const float*)d_in[9];
    const float* ln1g = (const float*)d_in[10];
    const float* ln1b = (const float*)d_in[11];
    const float* W1   = (const float*)d_in[12];
    const float* b1   = (const float*)d_in[13];
    const float* W2   = (const float*)d_in[14];
    const float* b2   = (const float*)d_in[15];
    const float* ln2g = (const float*)d_in[16];
    const float* ln2b = (const float*)d_in[17];
    float* out = (float*)d_out;

    float *bqkv;
    __half *qkvh, *hx, *hao, *hattn, *hh, *wh;
    cudaGetSymbolAddress((void**)&qkvh,  g_qkvh);
    cudaGetSymbolAddress((void**)&bqkv,  g_bqkv);
    cudaGetSymbolAddress((void**)&hx,    g_hx);
    cudaGetSymbolAddress((void**)&hao,   g_hao);
    cudaGetSymbolAddress((void**)&hattn, g_hattn);
    cudaGetSymbolAddress((void**)&hh,    g_hh);
    cudaGetSymbolAddress((void**)&wh,    g_wh);

    __half* proj_h = hh;     // reuse: hh free until FFN1 (which runs after LN1 consumes proj)
    __half* f2_h   = qkvh;   // reuse: qkvh dead after attention

    cudaFuncSetAttribute(attn_mma,        cudaFuncAttributeMaxDynamicSharedMemorySize, SMEM_ATT);
    cudaFuncSetAttribute(hgemm_kernel<0>, cudaFuncAttributeMaxDynamicSharedMemorySize, SMEM_GEMM);
    cudaFuncSetAttribute(hgemm_kernel<1>, cudaFuncAttributeMaxDynamicSharedMemorySize, SMEM_GEMM);
    cudaFuncSetAttribute(hgemm_kernel<2>, cudaFuncAttributeMaxDynamicSharedMemorySize, SMEM_GEMM);

    // #1: all prep (src f2h + weight transposes + bias pack)
    prep_kernel<<<28673, 256>>>(src, hx, Wq, Wk, Wv, Wo, W1, W2, bq, bk, bv, wh, bqkv);

    // #2: fused QKV projection -> half [M,3072]
    hgemm_kernel<2><<<dim3(24, 128), 256, SMEM_GEMM>>>(hx, wh + WQKV_OFF, bqkv, qkvh, M_, 3072, D_);

    // #3: fused tensor-core sparse attention -> hao (half)
    attn_mma<<<2048, 256, SMEM_ATT>>>(qkvh, hao);

    // #4: output projection -> half (into hh region; hx stays alive)
    hgemm_kernel<2><<<dim3(8, 128), 256, SMEM_GEMM>>>(hao, wh + WO_OFF, bo, proj_h, M_, D_, D_);

    // #5: hattn = LN1(src_h + proj) in half (feeds FFN1 and LN2 residual)
    add_ln_w_kernel<0><<<M_ / 8, 256>>>(hx, proj_h, ln1g, ln1b, nullptr, hattn);

    // #6,#7: FFN (FFN1 overwrites hh with the hidden activations)
    hgemm_kernel<1><<<dim3(32, 128), 256, SMEM_GEMM>>>(hattn, wh + W1_OFF, b1, hh, M_, DFF_, D_);
    hgemm_kernel<2><<<dim3(8, 128), 256, SMEM_GEMM>>>(hh, wh + W2_OFF, b2, f2_h, M_, D_, DFF_);

    // #8: out = LN2(hattn + ffn) -> fp32
    add_ln_w_kernel<1><<<M_ / 8, 256>>>(hattn, f2_h, ln2g, ln2b, out, nullptr);
}